// round 9
// baseline (speedup 1.0000x reference)
#include <cuda_runtime.h>
#include <cuda_bf16.h>
#include <math.h>

// ---------------- problem constants ----------------
#define TT    1024
#define BB    64
#define DIN   17
#define HM    150
#define GM    450       // 3*HM
#define HHD   128
#define GH    384       // 3*HHD
#define MSL   16        // measure length
#define NMEAS 64        // TT/MSL
#define NSEG  4096      // BB*NMEAS
#define HH2   256
#define NP    35
#define NK    15
#define NROW  65536     // TT*BB == MSL*NSEG

typedef unsigned long long u64;

// packed fp32x2 FMA (sm_103a): d = a*b + d, lanewise on (lo,hi)
#define FMA2(d, a, b) asm("fma.rn.f32x2 %0, %1, %2, %0;" : "+l"(d) : "l"(a), "l"(b))
// replicate one fp32 into both lanes of a pair
#define PACKR(p, f) asm("mov.b64 %0, {%1, %1};" : "=l"(p) : "r"(__float_as_uint(f)))

__device__ __forceinline__ float pair_lo(u64 p) { return __uint_as_float((unsigned)p); }
__device__ __forceinline__ float pair_hi(u64 p) { return __uint_as_float((unsigned)(p >> 32)); }
__device__ __forceinline__ u64 d2u_lo(double2 d) { return (u64)__double_as_longlong(d.x); }
__device__ __forceinline__ u64 d2u_hi(double2 d) { return (u64)__double_as_longlong(d.y); }

// ---------------- scratch (device globals; no allocation) ----------------
__device__ float g_gi_mf[NROW * GM];
__device__ float g_gi_mb[NROW * GM];
__device__ float g_rnn [NROW * 300];
__device__ float g_gi_hf[NROW * GH];
__device__ float g_gi_hb[NROW * GH];
__device__ float g_hier[NROW * HH2];
__device__ float g_q   [NROW * HH2];
__device__ float g_v   [NROW * HH2];
__device__ float g_ctx [NSEG * HH2];
__device__ float g_part[256 * 4];

// =====================================================================
// GEMM v3: C[r][j] = bias[j] + sum_k A[row(r)][k] * W[j][k]
// Tile 128x128, BK=16, 256 threads = 8 warps (4x2).
// Warp tile 32x64; lane layout 4x8 -> thread tile 8 rows x 8 cols.
// A LDS: 4 distinct addrs/warp (8x broadcast); W LDS: 8 distinct (4x bcast).
// Global->reg->smem double buffering hides L2 latency.
// MODE 0: row(r) = r;  MODE 1: hier segment remap.
// =====================================================================
#define SP 132  // smem pitch (floats)

template<int MODE>
__global__ __launch_bounds__(256)
void gemm_kernel(const float* __restrict__ A, const float* __restrict__ W,
                 const float* __restrict__ bias, float* __restrict__ C,
                 int K, int J) {
    __shared__ __align__(16) float As[16 * SP];   // [k][row]
    __shared__ __align__(16) float Ws[16 * SP];   // [k][col]
    const int tid  = threadIdx.x;
    const int warp = tid >> 5, lane = tid & 31;
    const int wm = warp >> 1, wn = warp & 1;      // 4 x 2 warp grid
    const int tr = lane >> 3, tc = lane & 7;      // 4 x 8 lanes
    const int row0 = wm * 32 + tr * 8;            // 8 consecutive rows
    const int col0 = wn * 64 + tc * 4;            // cols col0..+3 and col0+32..+35

    const int r0 = blockIdx.y * 128;
    const int j0 = blockIdx.x * 128;

    u64 acc[4][8];
#pragma unroll
    for (int i = 0; i < 4; i++)
#pragma unroll
        for (int j = 0; j < 8; j++) acc[i][j] = 0ull;

    // loader mapping: thread covers row lrow, k-halves lk0..lk0+7
    const int lrow = tid >> 1;
    const int lk0  = (tid & 1) * 8;
    int arow;
    {
        int r = r0 + lrow;
        if (MODE == 0) arow = r;
        else { int m = r >> 12, n2 = r & 4095; int b = n2 >> 6, s = n2 & 63;
               arow = ((s << 4) + m) * 64 + b; }
    }
    const float* Arow = A + (long)arow * K;
    const int wj = j0 + lrow;
    const bool wvalid = (wj < J);
    const float* Wrow = W + (long)(wvalid ? wj : 0) * K;

    const int ntiles = (K + 15) >> 4;
    float aR[8], wR[8];

    // prefetch tile 0
#pragma unroll
    for (int q = 0; q < 8; q++) {
        int k = lk0 + q;
        aR[q] = (k < K) ? Arow[k] : 0.f;
        wR[q] = (wvalid && k < K) ? Wrow[k] : 0.f;
    }
#pragma unroll
    for (int q = 0; q < 8; q++) {
        As[(lk0 + q) * SP + lrow] = aR[q];
        Ws[(lk0 + q) * SP + lrow] = wR[q];
    }
    __syncthreads();

    for (int t = 0; t < ntiles; t++) {
        // prefetch next tile into registers (overlaps with compute)
        const bool more = (t + 1 < ntiles);
        if (more) {
            int kb = (t + 1) * 16 + lk0;
#pragma unroll
            for (int q = 0; q < 8; q++) {
                int k = kb + q;
                aR[q] = (k < K) ? Arow[k] : 0.f;
                wR[q] = (wvalid && k < K) ? Wrow[k] : 0.f;
            }
        }
        // compute 16 k-steps from smem
#pragma unroll
        for (int kk = 0; kk < 16; kk++) {
            double2 a0 = *(const double2*)&As[kk * SP + row0];
            double2 a1 = *(const double2*)&As[kk * SP + row0 + 4];
            u64 ap[4] = { d2u_lo(a0), d2u_hi(a0), d2u_lo(a1), d2u_hi(a1) };
            float4 w0 = *(const float4*)&Ws[kk * SP + col0];
            float4 w1 = *(const float4*)&Ws[kk * SP + col0 + 32];
            u64 wp[8];
            PACKR(wp[0], w0.x); PACKR(wp[1], w0.y); PACKR(wp[2], w0.z); PACKR(wp[3], w0.w);
            PACKR(wp[4], w1.x); PACKR(wp[5], w1.y); PACKR(wp[6], w1.z); PACKR(wp[7], w1.w);
#pragma unroll
            for (int ip = 0; ip < 4; ip++)
#pragma unroll
                for (int j = 0; j < 8; j++)
                    FMA2(acc[ip][j], ap[ip], wp[j]);
        }
        if (more) {
            __syncthreads();
#pragma unroll
            for (int q = 0; q < 8; q++) {
                As[(lk0 + q) * SP + lrow] = aR[q];
                Ws[(lk0 + q) * SP + lrow] = wR[q];
            }
            __syncthreads();
        }
    }

    // epilogue: acc[ip][j] = rows (r0+row0+2ip, +1), col j<4 -> col0+j else col0+32+j-4
#pragma unroll
    for (int ip = 0; ip < 4; ip++) {
        long ra = r0 + row0 + 2 * ip;
#pragma unroll
        for (int j = 0; j < 8; j++) {
            int j_ = j0 + col0 + ((j < 4) ? j : (32 + j - 4));
            if (j_ < J) {
                float bb = bias[j_];
                C[ra * J + j_]       = pair_lo(acc[ip][j]) + bb;
                C[(ra + 1) * J + j_] = pair_hi(acc[ip][j]) + bb;
            }
        }
    }
}

// =====================================================================
// Main GRU recurrence: 128 blocks = (dir 2) x (batch 64), 480 threads.
// Whh[450][150]: cols 0..63 in smem (pitch 68), cols 64..149 in reg pairs.
// =====================================================================
__global__ __launch_bounds__(480, 1)
void main_gru_kernel(const float* __restrict__ gi_f, const float* __restrict__ gi_b,
                     const float* __restrict__ Whh_f, const float* __restrict__ Whh_b,
                     const float* __restrict__ bhh_f, const float* __restrict__ bhh_b,
                     float* __restrict__ rnn) {
    extern __shared__ __align__(16) float sm[];
    float* Ws   = sm;                 // 450*68
    float* h_s  = Ws + 450 * 68;      // 160 (150 used)
    float* gh_s = h_s + 160;          // 456 (450 used)

    const int tid = threadIdx.x;
    const int dir = blockIdx.x >> 6;
    const int b   = blockIdx.x & 63;
    const float* Whh = dir ? Whh_b : Whh_f;
    const float* bhh = dir ? bhh_b : bhh_f;
    const float* gi  = dir ? gi_b  : gi_f;

    for (int i = tid; i < 450 * 64; i += 480) {
        int g2 = i >> 6, k = i & 63;
        Ws[g2 * 68 + k] = Whh[g2 * 150 + k];
    }
    const int g = tid;
    u64 wp[43];          // col pairs (64+2i, 65+2i)
    float bh = 0.f;
    if (g < 450) {
        bh = bhh[g];
#pragma unroll
        for (int i = 0; i < 43; i++)
            wp[i] = *(const u64*)&Whh[g * 150 + 64 + 2 * i];
    }
    for (int i = tid; i < 160; i += 480) h_s[i] = 0.f;
    __syncthreads();

    for (int step = 0; step < TT; step++) {
        const int t = dir ? (TT - 1 - step) : step;
        float gir = 0.f, giz = 0.f, gin = 0.f;
        const long base = ((long)t * 64 + b) * GM;
        if (g < 150) {
            gir = gi[base + g];
            giz = gi[base + 150 + g];
            gin = gi[base + 300 + g];
        }
        if (g < 450) {
            u64 accp = 0ull;
#pragma unroll
            for (int k = 0; k < 64; k += 4) {
                double2 w2 = *(const double2*)&Ws[g * 68 + k];
                double2 h2 = *(const double2*)&h_s[k];
                FMA2(accp, d2u_lo(w2), d2u_lo(h2));
                FMA2(accp, d2u_hi(w2), d2u_hi(h2));
            }
#pragma unroll
            for (int q = 0; q < 21; q++) {
                double2 h2 = *(const double2*)&h_s[64 + 4 * q];
                FMA2(accp, wp[2 * q], d2u_lo(h2));
                FMA2(accp, wp[2 * q + 1], d2u_hi(h2));
            }
            {
                u64 hl = *(const u64*)&h_s[148];
                FMA2(accp, wp[42], hl);
            }
            gh_s[g] = pair_lo(accp) + pair_hi(accp) + bh;
        }
        __syncthreads();
        if (g < 150) {
            float r = 1.f / (1.f + expf(-(gir + gh_s[g])));
            float z = 1.f / (1.f + expf(-(giz + gh_s[150 + g])));
            float n = tanhf(gin + r * gh_s[300 + g]);
            float hn = (1.f - z) * n + z * h_s[g];
            h_s[g] = hn;
            rnn[((long)t * 64 + b) * 300 + dir * 150 + g] = hn;
        }
        __syncthreads();
    }
}

// =====================================================================
// Hier GRU: 1024 blocks = (dir 2) x (512 chain-groups), 8 chains/block,
// 384 threads. Whh[384][128] in smem (pitch 132). f32x2 matvec + gi prefetch.
// =====================================================================
#define HPITCH 132
__global__ __launch_bounds__(384, 1)
void hier_gru_kernel(const float* __restrict__ gi_f, const float* __restrict__ gi_b,
                     const float* __restrict__ Whh_f, const float* __restrict__ Whh_b,
                     const float* __restrict__ bhh_f, const float* __restrict__ bhh_b,
                     float* __restrict__ hier) {
    extern __shared__ __align__(16) float sm[];
    float* Ws   = sm;                    // 384*132
    float* h_s  = Ws + 384 * HPITCH;     // 8*128
    float* gh_s = h_s + 8 * 128;         // 8*384

    const int tid = threadIdx.x;
    const int dir = blockIdx.x >> 9;
    const int n2base = (blockIdx.x & 511) * 8;
    const float* Whh = dir ? Whh_b : Whh_f;
    const float* bhh = dir ? bhh_b : bhh_f;
    const float* gi  = dir ? gi_b  : gi_f;

    for (int i = tid; i < 384 * 128; i += 384) {
        int gg = i >> 7, k = i & 127;
        Ws[gg * HPITCH + k] = Whh[gg * 128 + k];
    }
    for (int i = tid; i < 8 * 128; i += 384) h_s[i] = 0.f;
    const int g = tid;
    const float bh = bhh[g];
    __syncthreads();

    for (int step = 0; step < MSL; step++) {
        const int m = dir ? (MSL - 1 - step) : step;
        float pg[3][3];
#pragma unroll
        for (int ii = 0; ii < 3; ii++) {
            int idx = tid + ii * 384;
            if (idx < 1024) {
                int c = idx >> 7, j = idx & 127;
                long gb = ((long)m * NSEG + (n2base + c)) * GH;
                pg[ii][0] = gi[gb + j];
                pg[ii][1] = gi[gb + 128 + j];
                pg[ii][2] = gi[gb + 256 + j];
            }
        }
        u64 accp[8];
#pragma unroll
        for (int c = 0; c < 8; c++) accp[c] = 0ull;
#pragma unroll 8
        for (int k = 0; k < 128; k += 4) {
            double2 w2 = *(const double2*)&Ws[g * HPITCH + k];
            u64 wlo = d2u_lo(w2), whi = d2u_hi(w2);
#pragma unroll
            for (int c = 0; c < 8; c++) {
                double2 h2 = *(const double2*)&h_s[c * 128 + k];
                FMA2(accp[c], wlo, d2u_lo(h2));
                FMA2(accp[c], whi, d2u_hi(h2));
            }
        }
#pragma unroll
        for (int c = 0; c < 8; c++)
            gh_s[c * 384 + g] = pair_lo(accp[c]) + pair_hi(accp[c]) + bh;
        __syncthreads();
#pragma unroll
        for (int ii = 0; ii < 3; ii++) {
            int idx = tid + ii * 384;
            if (idx < 1024) {
                int c = idx >> 7, j = idx & 127;
                int n2 = n2base + c;
                float r = 1.f / (1.f + expf(-(pg[ii][0] + gh_s[c * 384 + j])));
                float z = 1.f / (1.f + expf(-(pg[ii][1] + gh_s[c * 384 + 128 + j])));
                float n = tanhf(pg[ii][2] + r * gh_s[c * 384 + 256 + j]);
                float hn = (1.f - z) * n + z * h_s[c * 128 + j];
                h_s[c * 128 + j] = hn;
                hier[((long)m * NSEG + n2) * HH2 + dir * 128 + j] = hn;
            }
        }
        __syncthreads();
    }
}

// =====================================================================
// Attention per segment.
// =====================================================================
#define APITCH 261
__global__ __launch_bounds__(256)
void attn_kernel(const float* __restrict__ q, const float* __restrict__ v,
                 const float* __restrict__ hv, float* __restrict__ ctx) {
    extern __shared__ float smA[];
    float* qs = smA;
    float* vs = qs + 16 * APITCH;
    float* hs = vs + 16 * APITCH;
    float* ss = hs + 16 * APITCH;
    float* ws = ss + 16 * 17;

    const int tid = threadIdx.x;
    const int n2 = blockIdx.x;

    for (int i = tid; i < 16 * 256; i += 256) {
        int m = i >> 8, d = i & 255;
        long src = ((long)m * NSEG + n2) * HH2 + d;
        qs[m * APITCH + d] = q[src];
        vs[m * APITCH + d] = v[src];
        hs[m * APITCH + d] = hv[src];
    }
    __syncthreads();
    {
        int l = tid >> 4, mm = tid & 15;
        float acc = 0.f;
#pragma unroll 8
        for (int k = 0; k < 256; k++) acc += qs[l * APITCH + k] * vs[mm * APITCH + k];
        ss[l * 17 + mm] = acc;
    }
    __syncthreads();
    if (tid < 16) {
        int l = tid;
        float mx = -1e30f;
#pragma unroll
        for (int mm = 0; mm < 16; mm++) mx = fmaxf(mx, ss[l * 17 + mm]);
        float s = 0.f;
        float e[16];
#pragma unroll
        for (int mm = 0; mm < 16; mm++) { e[mm] = expf(ss[l * 17 + mm] - mx); s += e[mm]; }
        float inv = 1.f / s;
#pragma unroll
        for (int mm = 0; mm < 16; mm++) ss[l * 17 + mm] = e[mm] * inv;
    }
    __syncthreads();
    if (tid < 16) {
        int mm = tid;
        float s = 0.f;
#pragma unroll
        for (int l = 0; l < 16; l++) s += ss[l * 17 + mm];
        ws[mm] = s;
    }
    __syncthreads();
    {
        int d = tid;
        float acc = 0.f;
#pragma unroll
        for (int mm = 0; mm < 16; mm++) acc += ws[mm] * hs[mm * APITCH + d];
        ctx[(long)n2 * HH2 + d] = acc;
    }
}

// =====================================================================
// Fused output logits + masked CE; float4 activation loads.
// =====================================================================
__global__ __launch_bounds__(256, 1)
void ce_kernel(const float* __restrict__ rnn, const float* __restrict__ ctx,
               const float* __restrict__ Wp, const float* __restrict__ bp,
               const float* __restrict__ Wk, const float* __restrict__ bk,
               const int* __restrict__ pitches, const int* __restrict__ kss,
               float* __restrict__ part) {
    extern __shared__ __align__(16) float smC[];
    float* Wps = smC;                  // 35*556
    float* Wks = Wps + NP * 556;       // 15*256
    float* bps = Wks + NK * 256;       // 35
    float* bks = bps + NP;             // 15
    float* red = bks + NK;             // 256*4

    const int tid = threadIdx.x;
    for (int i = tid; i < NP * 556; i += 256) Wps[i] = Wp[i];
    for (int i = tid; i < NK * 256; i += 256) Wks[i] = Wk[i];
    if (tid < NP) bps[tid] = bp[tid];
    if (tid < NK) bks[tid] = bk[tid];
    __syncthreads();

    const int row = blockIdx.x * 256 + tid;
    const int t = row >> 6, b = row & 63;
    const int mi = t >> 4;
    const float* xr = rnn + (long)row * 300;
    const float* xc = ctx + ((long)(b * 64 + mi)) * HH2;

    float lg[NP], lgk[NK];
#pragma unroll
    for (int c = 0; c < NP; c++) lg[c] = bps[c];
#pragma unroll
    for (int c = 0; c < NK; c++) lgk[c] = bks[c];

    for (int k4 = 0; k4 < 75; k4++) {
        float4 x = *(const float4*)&xr[k4 * 4];
        const float* wrow = &Wps[k4 * 4];
#pragma unroll
        for (int c = 0; c < NP; c++) {
            const float* wr = wrow + c * 556;
            lg[c] += wr[0] * x.x + wr[1] * x.y + wr[2] * x.z + wr[3] * x.w;
        }
    }
    for (int k4 = 0; k4 < 64; k4++) {
        float4 x = *(const float4*)&xc[k4 * 4];
#pragma unroll
        for (int c = 0; c < NP; c++) {
            const float* wr = &Wps[c * 556 + 300 + k4 * 4];
            lg[c] += wr[0] * x.x + wr[1] * x.y + wr[2] * x.z + wr[3] * x.w;
        }
#pragma unroll
        for (int c = 0; c < NK; c++) {
            const float* wr = &Wks[c * 256 + k4 * 4];
            lgk[c] += wr[0] * x.x + wr[1] * x.y + wr[2] * x.z + wr[3] * x.w;
        }
    }

    int tp = pitches[row];
    float mx = -1e30f;
#pragma unroll
    for (int c = 0; c < NP; c++) mx = fmaxf(mx, lg[c]);
    float s = 0.f;
#pragma unroll
    for (int c = 0; c < NP; c++) s += expf(lg[c] - mx);
    float lsel = 0.f;
#pragma unroll
    for (int c = 0; c < NP; c++) lsel += (c == tp) ? lg[c] : 0.f;
    float nllp = 0.f, cp = 0.f;
    if (tp != 34) { nllp = (logf(s) + mx) - lsel; cp = 1.f; }

    int tk = kss[row];
    float mxk = -1e30f;
#pragma unroll
    for (int c = 0; c < NK; c++) mxk = fmaxf(mxk, lgk[c]);
    float sk = 0.f;
#pragma unroll
    for (int c = 0; c < NK; c++) sk += expf(lgk[c] - mxk);
    float ksel = 0.f;
#pragma unroll
    for (int c = 0; c < NK; c++) ksel += (c == tk) ? lgk[c] : 0.f;
    float nllk = 0.f, ck = 0.f;
    if (tk != 14) { nllk = (logf(sk) + mxk) - ksel; ck = 1.f; }

    red[tid] = nllp; red[256 + tid] = cp; red[512 + tid] = nllk; red[768 + tid] = ck;
    __syncthreads();
    for (int off = 128; off > 0; off >>= 1) {
        if (tid < off) {
            red[tid]       += red[tid + off];
            red[256 + tid] += red[256 + tid + off];
            red[512 + tid] += red[512 + tid + off];
            red[768 + tid] += red[768 + tid + off];
        }
        __syncthreads();
    }
    if (tid == 0) {
        part[blockIdx.x * 4 + 0] = red[0];
        part[blockIdx.x * 4 + 1] = red[256];
        part[blockIdx.x * 4 + 2] = red[512];
        part[blockIdx.x * 4 + 3] = red[768];
    }
}

__global__ __launch_bounds__(256)
void final_kernel(const float* __restrict__ part, float* __restrict__ out) {
    __shared__ float s0[256], s1[256], s2[256], s3[256];
    const int tid = threadIdx.x;
    s0[tid] = part[tid * 4 + 0];
    s1[tid] = part[tid * 4 + 1];
    s2[tid] = part[tid * 4 + 2];
    s3[tid] = part[tid * 4 + 3];
    __syncthreads();
    for (int off = 128; off > 0; off >>= 1) {
        if (tid < off) {
            s0[tid] += s0[tid + off]; s1[tid] += s1[tid + off];
            s2[tid] += s2[tid + off]; s3[tid] += s3[tid + off];
        }
        __syncthreads();
    }
    if (tid == 0)
        out[0] = s0[0] / fmaxf(s1[0], 1.f) + s2[0] / fmaxf(s3[0], 1.f);
}

// =====================================================================
// host
// =====================================================================
extern "C" void kernel_launch(void* const* d_in, const int* in_sizes, int n_in,
                              void* d_out, int out_size) {
    const float* sentences = (const float*)d_in[0];
    const int*   pitches   = (const int*)d_in[1];
    const int*   kss       = (const int*)d_in[2];
    const float* mWih_f = (const float*)d_in[5];
    const float* mWhh_f = (const float*)d_in[6];
    const float* mbih_f = (const float*)d_in[7];
    const float* mbhh_f = (const float*)d_in[8];
    const float* mWih_b = (const float*)d_in[9];
    const float* mWhh_b = (const float*)d_in[10];
    const float* mbih_b = (const float*)d_in[11];
    const float* mbhh_b = (const float*)d_in[12];
    const float* hWih_f = (const float*)d_in[13];
    const float* hWhh_f = (const float*)d_in[14];
    const float* hbih_f = (const float*)d_in[15];
    const float* hbhh_f = (const float*)d_in[16];
    const float* hWih_b = (const float*)d_in[17];
    const float* hWhh_b = (const float*)d_in[18];
    const float* hbih_b = (const float*)d_in[19];
    const float* hbhh_b = (const float*)d_in[20];
    const float* Wq = (const float*)d_in[21];
    const float* bq = (const float*)d_in[22];
    const float* Wv = (const float*)d_in[23];
    const float* bv = (const float*)d_in[24];
    const float* Wp = (const float*)d_in[25];
    const float* bp = (const float*)d_in[26];
    const float* Wk = (const float*)d_in[27];
    const float* bk = (const float*)d_in[28];
    float* out = (float*)d_out;

    float *p_gi_mf, *p_gi_mb, *p_rnn, *p_gi_hf, *p_gi_hb, *p_hier, *p_q, *p_v, *p_ctx, *p_part;
    cudaGetSymbolAddress((void**)&p_gi_mf, g_gi_mf);
    cudaGetSymbolAddress((void**)&p_gi_mb, g_gi_mb);
    cudaGetSymbolAddress((void**)&p_rnn,   g_rnn);
    cudaGetSymbolAddress((void**)&p_gi_hf, g_gi_hf);
    cudaGetSymbolAddress((void**)&p_gi_hb, g_gi_hb);
    cudaGetSymbolAddress((void**)&p_hier,  g_hier);
    cudaGetSymbolAddress((void**)&p_q,     g_q);
    cudaGetSymbolAddress((void**)&p_v,     g_v);
    cudaGetSymbolAddress((void**)&p_ctx,   g_ctx);
    cudaGetSymbolAddress((void**)&p_part,  g_part);

    const int SM_MAIN = (450 * 68 + 160 + 456) * 4;
    const int SM_HIER = (384 * HPITCH + 8 * 128 + 8 * 384) * 4;
    const int SM_ATTN = (3 * 16 * APITCH + 16 * 17 + 16) * 4;
    const int SM_CE   = (NP * 556 + NK * 256 + NP + NK + 1024) * 4;
    cudaFuncSetAttribute(main_gru_kernel, cudaFuncAttributeMaxDynamicSharedMemorySize, SM_MAIN);
    cudaFuncSetAttribute(hier_gru_kernel, cudaFuncAttributeMaxDynamicSharedMemorySize, SM_HIER);
    cudaFuncSetAttribute(attn_kernel,     cudaFuncAttributeMaxDynamicSharedMemorySize, SM_ATTN);
    cudaFuncSetAttribute(ce_kernel,       cudaFuncAttributeMaxDynamicSharedMemorySize, SM_CE);

    dim3 thr(256);
    // main input-side gates: [65536,17] @ [17,450]^T
    gemm_kernel<0><<<dim3((GM + 127) / 128, NROW / 128), thr>>>(sentences, mWih_f, mbih_f, p_gi_mf, DIN, GM);
    gemm_kernel<0><<<dim3((GM + 127) / 128, NROW / 128), thr>>>(sentences, mWih_b, mbih_b, p_gi_mb, DIN, GM);
    // main bi-GRU recurrence
    main_gru_kernel<<<128, 480, SM_MAIN>>>(p_gi_mf, p_gi_mb, mWhh_f, mWhh_b, mbhh_f, mbhh_b, p_rnn);
    // hier input-side gates (segment-remapped rows): [65536,300] @ [300,384]^T
    gemm_kernel<1><<<dim3(GH / 128, NROW / 128), thr>>>(p_rnn, hWih_f, hbih_f, p_gi_hf, 300, GH);
    gemm_kernel<1><<<dim3(GH / 128, NROW / 128), thr>>>(p_rnn, hWih_b, hbih_b, p_gi_hb, 300, GH);
    // hier bi-GRU
    hier_gru_kernel<<<1024, 384, SM_HIER>>>(p_gi_hf, p_gi_hb, hWhh_f, hWhh_b, hbhh_f, hbhh_b, p_hier);
    // q, v projections: [65536,256] @ [256,256]^T
    gemm_kernel<0><<<dim3(HH2 / 128, NROW / 128), thr>>>(p_hier, Wq, bq, p_q, HH2, HH2);
    gemm_kernel<0><<<dim3(HH2 / 128, NROW / 128), thr>>>(p_hier, Wv, bv, p_v, HH2, HH2);
    // attention + context
    attn_kernel<<<NSEG, 256, SM_ATTN>>>(p_q, p_v, p_hier, p_ctx);
    // fused logits + CE partials
    ce_kernel<<<NROW / 256, 256, SM_CE>>>(p_rnn, p_ctx, Wp, bp, Wk, bk, pitches, kss, p_part);
    // final reduce -> loss
    final_kernel<<<1, 256>>>(p_part, out);
}

// round 11
// speedup vs baseline: 1.0023x; 1.0023x over previous
#include <cuda_runtime.h>
#include <cuda_bf16.h>
#include <math.h>

// ---------------- problem constants ----------------
#define TT    1024
#define BB    64
#define DIN   17
#define HM    150
#define GM    450       // 3*HM
#define HHD   128
#define GH    384       // 3*HHD
#define MSL   16        // measure length
#define NMEAS 64        // TT/MSL
#define NSEG  4096      // BB*NMEAS
#define HH2   256
#define NP    35
#define NK    15
#define NROW  65536     // TT*BB == MSL*NSEG

typedef unsigned long long u64;

// packed fp32x2 FMA (sm_103a): d = a*b + d, lanewise on (lo,hi)
#define FMA2(d, a, b) asm("fma.rn.f32x2 %0, %1, %2, %0;" : "+l"(d) : "l"(a), "l"(b))
// replicate one fp32 into both lanes of a pair
#define PACKR(p, f) asm("mov.b64 %0, {%1, %1};" : "=l"(p) : "r"(__float_as_uint(f)))

__device__ __forceinline__ float pair_lo(u64 p) { return __uint_as_float((unsigned)p); }
__device__ __forceinline__ float pair_hi(u64 p) { return __uint_as_float((unsigned)(p >> 32)); }
__device__ __forceinline__ u64 d2u_lo(double2 d) { return (u64)__double_as_longlong(d.x); }
__device__ __forceinline__ u64 d2u_hi(double2 d) { return (u64)__double_as_longlong(d.y); }

// ---------------- scratch (device globals; no allocation) ----------------
__device__ float g_gi_mf[NROW * GM];
__device__ float g_gi_mb[NROW * GM];
__device__ float g_rnn [NROW * 300];
__device__ float g_gi_hf[NROW * GH];
__device__ float g_gi_hb[NROW * GH];
__device__ float g_hier[NROW * HH2];
__device__ float g_q   [NROW * HH2];
__device__ float g_v   [NROW * HH2];
__device__ float g_ctx [NSEG * HH2];
__device__ float g_part[256 * 4];

// =====================================================================
// GEMM v3: C[r][j] = bias[j] + sum_k A[row(r)][k] * W[j][k]
// Tile 128x128, BK=16, 256 threads = 8 warps (4x2).
// Warp tile 32x64; lane layout 4x8 -> thread tile 8 rows x 8 cols.
// A LDS: 4 distinct addrs/warp (8x broadcast); W LDS: 8 distinct (4x bcast).
// Global->reg->smem double buffering hides L2 latency.
// MODE 0: row(r) = r;  MODE 1: hier segment remap.
// =====================================================================
#define SP 132  // smem pitch (floats)

template<int MODE>
__global__ __launch_bounds__(256)
void gemm_kernel(const float* __restrict__ A, const float* __restrict__ W,
                 const float* __restrict__ bias, float* __restrict__ C,
                 int K, int J) {
    __shared__ __align__(16) float As[16 * SP];   // [k][row]
    __shared__ __align__(16) float Ws[16 * SP];   // [k][col]
    const int tid  = threadIdx.x;
    const int warp = tid >> 5, lane = tid & 31;
    const int wm = warp >> 1, wn = warp & 1;      // 4 x 2 warp grid
    const int tr = lane >> 3, tc = lane & 7;      // 4 x 8 lanes
    const int row0 = wm * 32 + tr * 8;            // 8 consecutive rows
    const int col0 = wn * 64 + tc * 4;            // cols col0..+3 and col0+32..+35

    const int r0 = blockIdx.y * 128;
    const int j0 = blockIdx.x * 128;

    u64 acc[4][8];
#pragma unroll
    for (int i = 0; i < 4; i++)
#pragma unroll
        for (int j = 0; j < 8; j++) acc[i][j] = 0ull;

    // loader mapping: thread covers row lrow, k-halves lk0..lk0+7
    const int lrow = tid >> 1;
    const int lk0  = (tid & 1) * 8;
    int arow;
    {
        int r = r0 + lrow;
        if (MODE == 0) arow = r;
        else { int m = r >> 12, n2 = r & 4095; int b = n2 >> 6, s = n2 & 63;
               arow = ((s << 4) + m) * 64 + b; }
    }
    const float* Arow = A + (long)arow * K;
    const int wj = j0 + lrow;
    const bool wvalid = (wj < J);
    const float* Wrow = W + (long)(wvalid ? wj : 0) * K;

    const int ntiles = (K + 15) >> 4;
    float aR[8], wR[8];

    // prefetch tile 0
#pragma unroll
    for (int q = 0; q < 8; q++) {
        int k = lk0 + q;
        aR[q] = (k < K) ? Arow[k] : 0.f;
        wR[q] = (wvalid && k < K) ? Wrow[k] : 0.f;
    }
#pragma unroll
    for (int q = 0; q < 8; q++) {
        As[(lk0 + q) * SP + lrow] = aR[q];
        Ws[(lk0 + q) * SP + lrow] = wR[q];
    }
    __syncthreads();

    for (int t = 0; t < ntiles; t++) {
        // prefetch next tile into registers (overlaps with compute)
        const bool more = (t + 1 < ntiles);
        if (more) {
            int kb = (t + 1) * 16 + lk0;
#pragma unroll
            for (int q = 0; q < 8; q++) {
                int k = kb + q;
                aR[q] = (k < K) ? Arow[k] : 0.f;
                wR[q] = (wvalid && k < K) ? Wrow[k] : 0.f;
            }
        }
        // compute 16 k-steps from smem
#pragma unroll
        for (int kk = 0; kk < 16; kk++) {
            double2 a0 = *(const double2*)&As[kk * SP + row0];
            double2 a1 = *(const double2*)&As[kk * SP + row0 + 4];
            u64 ap[4] = { d2u_lo(a0), d2u_hi(a0), d2u_lo(a1), d2u_hi(a1) };
            float4 w0 = *(const float4*)&Ws[kk * SP + col0];
            float4 w1 = *(const float4*)&Ws[kk * SP + col0 + 32];
            u64 wp[8];
            PACKR(wp[0], w0.x); PACKR(wp[1], w0.y); PACKR(wp[2], w0.z); PACKR(wp[3], w0.w);
            PACKR(wp[4], w1.x); PACKR(wp[5], w1.y); PACKR(wp[6], w1.z); PACKR(wp[7], w1.w);
#pragma unroll
            for (int ip = 0; ip < 4; ip++)
#pragma unroll
                for (int j = 0; j < 8; j++)
                    FMA2(acc[ip][j], ap[ip], wp[j]);
        }
        if (more) {
            __syncthreads();
#pragma unroll
            for (int q = 0; q < 8; q++) {
                As[(lk0 + q) * SP + lrow] = aR[q];
                Ws[(lk0 + q) * SP + lrow] = wR[q];
            }
            __syncthreads();
        }
    }

    // epilogue: acc[ip][j] = rows (r0+row0+2ip, +1), col j<4 -> col0+j else col0+32+j-4
#pragma unroll
    for (int ip = 0; ip < 4; ip++) {
        long ra = r0 + row0 + 2 * ip;
#pragma unroll
        for (int j = 0; j < 8; j++) {
            int j_ = j0 + col0 + ((j < 4) ? j : (32 + j - 4));
            if (j_ < J) {
                float bb = bias[j_];
                C[ra * J + j_]       = pair_lo(acc[ip][j]) + bb;
                C[(ra + 1) * J + j_] = pair_hi(acc[ip][j]) + bb;
            }
        }
    }
}

// =====================================================================
// Main GRU recurrence: 128 blocks = (dir 2) x (batch 64), 480 threads.
// Whh[450][150]: cols 0..63 in smem (pitch 68), cols 64..149 in reg pairs.
// =====================================================================
__global__ __launch_bounds__(480, 1)
void main_gru_kernel(const float* __restrict__ gi_f, const float* __restrict__ gi_b,
                     const float* __restrict__ Whh_f, const float* __restrict__ Whh_b,
                     const float* __restrict__ bhh_f, const float* __restrict__ bhh_b,
                     float* __restrict__ rnn) {
    extern __shared__ __align__(16) float sm[];
    float* Ws   = sm;                 // 450*68
    float* h_s  = Ws + 450 * 68;      // 160 (150 used)
    float* gh_s = h_s + 160;          // 456 (450 used)

    const int tid = threadIdx.x;
    const int dir = blockIdx.x >> 6;
    const int b   = blockIdx.x & 63;
    const float* Whh = dir ? Whh_b : Whh_f;
    const float* bhh = dir ? bhh_b : bhh_f;
    const float* gi  = dir ? gi_b  : gi_f;

    for (int i = tid; i < 450 * 64; i += 480) {
        int g2 = i >> 6, k = i & 63;
        Ws[g2 * 68 + k] = Whh[g2 * 150 + k];
    }
    const int g = tid;
    u64 wp[43];          // col pairs (64+2i, 65+2i)
    float bh = 0.f;
    if (g < 450) {
        bh = bhh[g];
#pragma unroll
        for (int i = 0; i < 43; i++)
            wp[i] = *(const u64*)&Whh[g * 150 + 64 + 2 * i];
    }
    for (int i = tid; i < 160; i += 480) h_s[i] = 0.f;
    __syncthreads();

    for (int step = 0; step < TT; step++) {
        const int t = dir ? (TT - 1 - step) : step;
        float gir = 0.f, giz = 0.f, gin = 0.f;
        const long base = ((long)t * 64 + b) * GM;
        if (g < 150) {
            gir = gi[base + g];
            giz = gi[base + 150 + g];
            gin = gi[base + 300 + g];
        }
        if (g < 450) {
            u64 accp = 0ull;
#pragma unroll
            for (int k = 0; k < 64; k += 4) {
                double2 w2 = *(const double2*)&Ws[g * 68 + k];
                double2 h2 = *(const double2*)&h_s[k];
                FMA2(accp, d2u_lo(w2), d2u_lo(h2));
                FMA2(accp, d2u_hi(w2), d2u_hi(h2));
            }
#pragma unroll
            for (int q = 0; q < 21; q++) {
                double2 h2 = *(const double2*)&h_s[64 + 4 * q];
                FMA2(accp, wp[2 * q], d2u_lo(h2));
                FMA2(accp, wp[2 * q + 1], d2u_hi(h2));
            }
            {
                u64 hl = *(const u64*)&h_s[148];
                FMA2(accp, wp[42], hl);
            }
            gh_s[g] = pair_lo(accp) + pair_hi(accp) + bh;
        }
        __syncthreads();
        if (g < 150) {
            float r = 1.f / (1.f + expf(-(gir + gh_s[g])));
            float z = 1.f / (1.f + expf(-(giz + gh_s[150 + g])));
            float n = tanhf(gin + r * gh_s[300 + g]);
            float hn = (1.f - z) * n + z * h_s[g];
            h_s[g] = hn;
            rnn[((long)t * 64 + b) * 300 + dir * 150 + g] = hn;
        }
        __syncthreads();
    }
}

// =====================================================================
// Hier GRU: 1024 blocks = (dir 2) x (512 chain-groups), 8 chains/block,
// 384 threads. Whh[384][128] in smem (pitch 132). f32x2 matvec + gi prefetch.
// =====================================================================
#define HPITCH 132
__global__ __launch_bounds__(384, 1)
void hier_gru_kernel(const float* __restrict__ gi_f, const float* __restrict__ gi_b,
                     const float* __restrict__ Whh_f, const float* __restrict__ Whh_b,
                     const float* __restrict__ bhh_f, const float* __restrict__ bhh_b,
                     float* __restrict__ hier) {
    extern __shared__ __align__(16) float sm[];
    float* Ws   = sm;                    // 384*132
    float* h_s  = Ws + 384 * HPITCH;     // 8*128
    float* gh_s = h_s + 8 * 128;         // 8*384

    const int tid = threadIdx.x;
    const int dir = blockIdx.x >> 9;
    const int n2base = (blockIdx.x & 511) * 8;
    const float* Whh = dir ? Whh_b : Whh_f;
    const float* bhh = dir ? bhh_b : bhh_f;
    const float* gi  = dir ? gi_b  : gi_f;

    for (int i = tid; i < 384 * 128; i += 384) {
        int gg = i >> 7, k = i & 127;
        Ws[gg * HPITCH + k] = Whh[gg * 128 + k];
    }
    for (int i = tid; i < 8 * 128; i += 384) h_s[i] = 0.f;
    const int g = tid;
    const float bh = bhh[g];
    __syncthreads();

    for (int step = 0; step < MSL; step++) {
        const int m = dir ? (MSL - 1 - step) : step;
        float pg[3][3];
#pragma unroll
        for (int ii = 0; ii < 3; ii++) {
            int idx = tid + ii * 384;
            if (idx < 1024) {
                int c = idx >> 7, j = idx & 127;
                long gb = ((long)m * NSEG + (n2base + c)) * GH;
                pg[ii][0] = gi[gb + j];
                pg[ii][1] = gi[gb + 128 + j];
                pg[ii][2] = gi[gb + 256 + j];
            }
        }
        u64 accp[8];
#pragma unroll
        for (int c = 0; c < 8; c++) accp[c] = 0ull;
#pragma unroll 8
        for (int k = 0; k < 128; k += 4) {
            double2 w2 = *(const double2*)&Ws[g * HPITCH + k];
            u64 wlo = d2u_lo(w2), whi = d2u_hi(w2);
#pragma unroll
            for (int c = 0; c < 8; c++) {
                double2 h2 = *(const double2*)&h_s[c * 128 + k];
                FMA2(accp[c], wlo, d2u_lo(h2));
                FMA2(accp[c], whi, d2u_hi(h2));
            }
        }
#pragma unroll
        for (int c = 0; c < 8; c++)
            gh_s[c * 384 + g] = pair_lo(accp[c]) + pair_hi(accp[c]) + bh;
        __syncthreads();
#pragma unroll
        for (int ii = 0; ii < 3; ii++) {
            int idx = tid + ii * 384;
            if (idx < 1024) {
                int c = idx >> 7, j = idx & 127;
                int n2 = n2base + c;
                float r = 1.f / (1.f + expf(-(pg[ii][0] + gh_s[c * 384 + j])));
                float z = 1.f / (1.f + expf(-(pg[ii][1] + gh_s[c * 384 + 128 + j])));
                float n = tanhf(pg[ii][2] + r * gh_s[c * 384 + 256 + j]);
                float hn = (1.f - z) * n + z * h_s[c * 128 + j];
                h_s[c * 128 + j] = hn;
                hier[((long)m * NSEG + n2) * HH2 + dir * 128 + j] = hn;
            }
        }
        __syncthreads();
    }
}

// =====================================================================
// Attention per segment.
// =====================================================================
#define APITCH 261
__global__ __launch_bounds__(256)
void attn_kernel(const float* __restrict__ q, const float* __restrict__ v,
                 const float* __restrict__ hv, float* __restrict__ ctx) {
    extern __shared__ float smA[];
    float* qs = smA;
    float* vs = qs + 16 * APITCH;
    float* hs = vs + 16 * APITCH;
    float* ss = hs + 16 * APITCH;
    float* ws = ss + 16 * 17;

    const int tid = threadIdx.x;
    const int n2 = blockIdx.x;

    for (int i = tid; i < 16 * 256; i += 256) {
        int m = i >> 8, d = i & 255;
        long src = ((long)m * NSEG + n2) * HH2 + d;
        qs[m * APITCH + d] = q[src];
        vs[m * APITCH + d] = v[src];
        hs[m * APITCH + d] = hv[src];
    }
    __syncthreads();
    {
        int l = tid >> 4, mm = tid & 15;
        float acc = 0.f;
#pragma unroll 8
        for (int k = 0; k < 256; k++) acc += qs[l * APITCH + k] * vs[mm * APITCH + k];
        ss[l * 17 + mm] = acc;
    }
    __syncthreads();
    if (tid < 16) {
        int l = tid;
        float mx = -1e30f;
#pragma unroll
        for (int mm = 0; mm < 16; mm++) mx = fmaxf(mx, ss[l * 17 + mm]);
        float s = 0.f;
        float e[16];
#pragma unroll
        for (int mm = 0; mm < 16; mm++) { e[mm] = expf(ss[l * 17 + mm] - mx); s += e[mm]; }
        float inv = 1.f / s;
#pragma unroll
        for (int mm = 0; mm < 16; mm++) ss[l * 17 + mm] = e[mm] * inv;
    }
    __syncthreads();
    if (tid < 16) {
        int mm = tid;
        float s = 0.f;
#pragma unroll
        for (int l = 0; l < 16; l++) s += ss[l * 17 + mm];
        ws[mm] = s;
    }
    __syncthreads();
    {
        int d = tid;
        float acc = 0.f;
#pragma unroll
        for (int mm = 0; mm < 16; mm++) acc += ws[mm] * hs[mm * APITCH + d];
        ctx[(long)n2 * HH2 + d] = acc;
    }
}

// =====================================================================
// Fused output logits + masked CE; float4 activation loads.
// =====================================================================
__global__ __launch_bounds__(256, 1)
void ce_kernel(const float* __restrict__ rnn, const float* __restrict__ ctx,
               const float* __restrict__ Wp, const float* __restrict__ bp,
               const float* __restrict__ Wk, const float* __restrict__ bk,
               const int* __restrict__ pitches, const int* __restrict__ kss,
               float* __restrict__ part) {
    extern __shared__ __align__(16) float smC[];
    float* Wps = smC;                  // 35*556
    float* Wks = Wps + NP * 556;       // 15*256
    float* bps = Wks + NK * 256;       // 35
    float* bks = bps + NP;             // 15
    float* red = bks + NK;             // 256*4

    const int tid = threadIdx.x;
    for (int i = tid; i < NP * 556; i += 256) Wps[i] = Wp[i];
    for (int i = tid; i < NK * 256; i += 256) Wks[i] = Wk[i];
    if (tid < NP) bps[tid] = bp[tid];
    if (tid < NK) bks[tid] = bk[tid];
    __syncthreads();

    const int row = blockIdx.x * 256 + tid;
    const int t = row >> 6, b = row & 63;
    const int mi = t >> 4;
    const float* xr = rnn + (long)row * 300;
    const float* xc = ctx + ((long)(b * 64 + mi)) * HH2;

    float lg[NP], lgk[NK];
#pragma unroll
    for (int c = 0; c < NP; c++) lg[c] = bps[c];
#pragma unroll
    for (int c = 0; c < NK; c++) lgk[c] = bks[c];

    for (int k4 = 0; k4 < 75; k4++) {
        float4 x = *(const float4*)&xr[k4 * 4];
        const float* wrow = &Wps[k4 * 4];
#pragma unroll
        for (int c = 0; c < NP; c++) {
            const float* wr = wrow + c * 556;
            lg[c] += wr[0] * x.x + wr[1] * x.y + wr[2] * x.z + wr[3] * x.w;
        }
    }
    for (int k4 = 0; k4 < 64; k4++) {
        float4 x = *(const float4*)&xc[k4 * 4];
#pragma unroll
        for (int c = 0; c < NP; c++) {
            const float* wr = &Wps[c * 556 + 300 + k4 * 4];
            lg[c] += wr[0] * x.x + wr[1] * x.y + wr[2] * x.z + wr[3] * x.w;
        }
#pragma unroll
        for (int c = 0; c < NK; c++) {
            const float* wr = &Wks[c * 256 + k4 * 4];
            lgk[c] += wr[0] * x.x + wr[1] * x.y + wr[2] * x.z + wr[3] * x.w;
        }
    }

    int tp = pitches[row];
    float mx = -1e30f;
#pragma unroll
    for (int c = 0; c < NP; c++) mx = fmaxf(mx, lg[c]);
    float s = 0.f;
#pragma unroll
    for (int c = 0; c < NP; c++) s += expf(lg[c] - mx);
    float lsel = 0.f;
#pragma unroll
    for (int c = 0; c < NP; c++) lsel += (c == tp) ? lg[c] : 0.f;
    float nllp = 0.f, cp = 0.f;
    if (tp != 34) { nllp = (logf(s) + mx) - lsel; cp = 1.f; }

    int tk = kss[row];
    float mxk = -1e30f;
#pragma unroll
    for (int c = 0; c < NK; c++) mxk = fmaxf(mxk, lgk[c]);
    float sk = 0.f;
#pragma unroll
    for (int c = 0; c < NK; c++) sk += expf(lgk[c] - mxk);
    float ksel = 0.f;
#pragma unroll
    for (int c = 0; c < NK; c++) ksel += (c == tk) ? lgk[c] : 0.f;
    float nllk = 0.f, ck = 0.f;
    if (tk != 14) { nllk = (logf(sk) + mxk) - ksel; ck = 1.f; }

    red[tid] = nllp; red[256 + tid] = cp; red[512 + tid] = nllk; red[768 + tid] = ck;
    __syncthreads();
    for (int off = 128; off > 0; off >>= 1) {
        if (tid < off) {
            red[tid]       += red[tid + off];
            red[256 + tid] += red[256 + tid + off];
            red[512 + tid] += red[512 + tid + off];
            red[768 + tid] += red[768 + tid + off];
        }
        __syncthreads();
    }
    if (tid == 0) {
        part[blockIdx.x * 4 + 0] = red[0];
        part[blockIdx.x * 4 + 1] = red[256];
        part[blockIdx.x * 4 + 2] = red[512];
        part[blockIdx.x * 4 + 3] = red[768];
    }
}

__global__ __launch_bounds__(256)
void final_kernel(const float* __restrict__ part, float* __restrict__ out) {
    __shared__ float s0[256], s1[256], s2[256], s3[256];
    const int tid = threadIdx.x;
    s0[tid] = part[tid * 4 + 0];
    s1[tid] = part[tid * 4 + 1];
    s2[tid] = part[tid * 4 + 2];
    s3[tid] = part[tid * 4 + 3];
    __syncthreads();
    for (int off = 128; off > 0; off >>= 1) {
        if (tid < off) {
            s0[tid] += s0[tid + off]; s1[tid] += s1[tid + off];
            s2[tid] += s2[tid + off]; s3[tid] += s3[tid + off];
        }
        __syncthreads();
    }
    if (tid == 0)
        out[0] = s0[0] / fmaxf(s1[0], 1.f) + s2[0] / fmaxf(s3[0], 1.f);
}

// =====================================================================
// host
// =====================================================================
extern "C" void kernel_launch(void* const* d_in, const int* in_sizes, int n_in,
                              void* d_out, int out_size) {
    const float* sentences = (const float*)d_in[0];
    const int*   pitches   = (const int*)d_in[1];
    const int*   kss       = (const int*)d_in[2];
    const float* mWih_f = (const float*)d_in[5];
    const float* mWhh_f = (const float*)d_in[6];
    const float* mbih_f = (const float*)d_in[7];
    const float* mbhh_f = (const float*)d_in[8];
    const float* mWih_b = (const float*)d_in[9];
    const float* mWhh_b = (const float*)d_in[10];
    const float* mbih_b = (const float*)d_in[11];
    const float* mbhh_b = (const float*)d_in[12];
    const float* hWih_f = (const float*)d_in[13];
    const float* hWhh_f = (const float*)d_in[14];
    const float* hbih_f = (const float*)d_in[15];
    const float* hbhh_f = (const float*)d_in[16];
    const float* hWih_b = (const float*)d_in[17];
    const float* hWhh_b = (const float*)d_in[18];
    const float* hbih_b = (const float*)d_in[19];
    const float* hbhh_b = (const float*)d_in[20];
    const float* Wq = (const float*)d_in[21];
    const float* bq = (const float*)d_in[22];
    const float* Wv = (const float*)d_in[23];
    const float* bv = (const float*)d_in[24];
    const float* Wp = (const float*)d_in[25];
    const float* bp = (const float*)d_in[26];
    const float* Wk = (const float*)d_in[27];
    const float* bk = (const float*)d_in[28];
    float* out = (float*)d_out;

    float *p_gi_mf, *p_gi_mb, *p_rnn, *p_gi_hf, *p_gi_hb, *p_hier, *p_q, *p_v, *p_ctx, *p_part;
    cudaGetSymbolAddress((void**)&p_gi_mf, g_gi_mf);
    cudaGetSymbolAddress((void**)&p_gi_mb, g_gi_mb);
    cudaGetSymbolAddress((void**)&p_rnn,   g_rnn);
    cudaGetSymbolAddress((void**)&p_gi_hf, g_gi_hf);
    cudaGetSymbolAddress((void**)&p_gi_hb, g_gi_hb);
    cudaGetSymbolAddress((void**)&p_hier,  g_hier);
    cudaGetSymbolAddress((void**)&p_q,     g_q);
    cudaGetSymbolAddress((void**)&p_v,     g_v);
    cudaGetSymbolAddress((void**)&p_ctx,   g_ctx);
    cudaGetSymbolAddress((void**)&p_part,  g_part);

    const int SM_MAIN = (450 * 68 + 160 + 456) * 4;
    const int SM_HIER = (384 * HPITCH + 8 * 128 + 8 * 384) * 4;
    const int SM_ATTN = (3 * 16 * APITCH + 16 * 17 + 16) * 4;
    const int SM_CE   = (NP * 556 + NK * 256 + NP + NK + 1024) * 4;
    cudaFuncSetAttribute(main_gru_kernel, cudaFuncAttributeMaxDynamicSharedMemorySize, SM_MAIN);
    cudaFuncSetAttribute(hier_gru_kernel, cudaFuncAttributeMaxDynamicSharedMemorySize, SM_HIER);
    cudaFuncSetAttribute(attn_kernel,     cudaFuncAttributeMaxDynamicSharedMemorySize, SM_ATTN);
    cudaFuncSetAttribute(ce_kernel,       cudaFuncAttributeMaxDynamicSharedMemorySize, SM_CE);

    dim3 thr(256);
    // main input-side gates: [65536,17] @ [17,450]^T
    gemm_kernel<0><<<dim3((GM + 127) / 128, NROW / 128), thr>>>(sentences, mWih_f, mbih_f, p_gi_mf, DIN, GM);
    gemm_kernel<0><<<dim3((GM + 127) / 128, NROW / 128), thr>>>(sentences, mWih_b, mbih_b, p_gi_mb, DIN, GM);
    // main bi-GRU recurrence
    main_gru_kernel<<<128, 480, SM_MAIN>>>(p_gi_mf, p_gi_mb, mWhh_f, mWhh_b, mbhh_f, mbhh_b, p_rnn);
    // hier input-side gates (segment-remapped rows): [65536,300] @ [300,384]^T
    gemm_kernel<1><<<dim3(GH / 128, NROW / 128), thr>>>(p_rnn, hWih_f, hbih_f, p_gi_hf, 300, GH);
    gemm_kernel<1><<<dim3(GH / 128, NROW / 128), thr>>>(p_rnn, hWih_b, hbih_b, p_gi_hb, 300, GH);
    // hier bi-GRU
    hier_gru_kernel<<<1024, 384, SM_HIER>>>(p_gi_hf, p_gi_hb, hWhh_f, hWhh_b, hbhh_f, hbhh_b, p_hier);
    // q, v projections: [65536,256] @ [256,256]^T
    gemm_kernel<0><<<dim3(HH2 / 128, NROW / 128), thr>>>(p_hier, Wq, bq, p_q, HH2, HH2);
    gemm_kernel<0><<<dim3(HH2 / 128, NROW / 128), thr>>>(p_hier, Wv, bv, p_v, HH2, HH2);
    // attention + context
    attn_kernel<<<NSEG, 256, SM_ATTN>>>(p_q, p_v, p_hier, p_ctx);
    // fused logits + CE partials
    ce_kernel<<<NROW / 256, 256, SM_CE>>>(p_rnn, p_ctx, Wp, bp, Wk, bk, pitches, kss, p_part);
    // final reduce -> loss
    final_kernel<<<1, 256>>>(p_part, out);
}

// round 14
// speedup vs baseline: 1.2677x; 1.2648x over previous
#include <cuda_runtime.h>
#include <cuda_bf16.h>
#include <math.h>
#include <stdint.h>

#define TT 1024
#define BB 64
#define DIN 17
#define HM 150
#define GM 450
#define GH 384
#define MSL 16
#define NSEG 4096
#define HH2 256
#define NP 35
#define NK 15
#define NROW 65536
#define KP1 320

typedef unsigned long long u64;

#define FMA2(d, a, b) asm("fma.rn.f32x2 %0, %1, %2, %0;" : "+l"(d) : "l"(a), "l"(b))
__device__ __forceinline__ float pair_lo(u64 p) { return __uint_as_float((unsigned)p); }
__device__ __forceinline__ float pair_hi(u64 p) { return __uint_as_float((unsigned)(p >> 32)); }
__device__ __forceinline__ u64 d2u_lo(double2 d) { return (u64)__double_as_longlong(d.x); }
__device__ __forceinline__ u64 d2u_hi(double2 d) { return (u64)__double_as_longlong(d.y); }

__device__ __forceinline__ uint32_t smem_u32_of(const void* p) {
    uint32_t a;
    asm("{ .reg .u64 t; cvta.to.shared.u64 t, %1; cvt.u32.u64 %0, t; }" : "=r"(a) : "l"(p));
    return a;
}
#define SWZ(b) ((b) ^ (((b) >> 3) & 0x70))

__device__ __forceinline__ void cp16(uint32_t dst, const void* src) {
    asm volatile("cp.async.cg.shared.global [%0], [%1], 16;" :: "r"(dst), "l"(src) : "memory");
}
__device__ __forceinline__ void ldm4(uint32_t* r, uint32_t addr) {
    asm volatile("ldmatrix.sync.aligned.m8n8.x4.shared.b16 {%0,%1,%2,%3}, [%4];"
                 : "=r"(r[0]), "=r"(r[1]), "=r"(r[2]), "=r"(r[3]) : "r"(addr));
}
__device__ __forceinline__ void mma16816(float* d, const uint32_t* a, const uint32_t* b) {
    asm volatile("mma.sync.aligned.m16n8k16.row.col.f32.bf16.bf16.f32 "
                 "{%0,%1,%2,%3}, {%4,%5,%6,%7}, {%8,%9}, {%0,%1,%2,%3};"
                 : "+f"(d[0]), "+f"(d[1]), "+f"(d[2]), "+f"(d[3])
                 : "r"(a[0]), "r"(a[1]), "r"(a[2]), "r"(a[3]), "r"(b[0]), "r"(b[1]));
}

// ---------------- scratch ----------------
__device__ float g_rnn [NROW * 300];
__device__ float g_gi_hf[NROW * GH];
__device__ float g_gi_hb[NROW * GH];
__device__ float g_hier[NROW * HH2];
__device__ float g_q   [NROW * HH2];
__device__ float g_v   [NROW * HH2];
__device__ float g_ctx [NSEG * HH2];
__device__ float g_part[256 * 4];
__device__ __nv_bfloat16 g_rnn_hi[NROW * KP1];
__device__ __nv_bfloat16 g_rnn_lo[NROW * KP1];
__device__ __nv_bfloat16 g_hier_hi[NROW * HH2];
__device__ __nv_bfloat16 g_hier_lo[NROW * HH2];
__device__ __nv_bfloat16 g_wh_hi[2 * GH * KP1];
__device__ __nv_bfloat16 g_wh_lo[2 * GH * KP1];
__device__ __nv_bfloat16 g_wqv_hi[2 * HH2 * HH2];
__device__ __nv_bfloat16 g_wqv_lo[2 * HH2 * HH2];

// ---------------- weight hi/lo split ----------------
__global__ void conv_w_kernel(const float* __restrict__ hWf, const float* __restrict__ hWb,
                              const float* __restrict__ Wq, const float* __restrict__ Wv,
                              __nv_bfloat16* __restrict__ whh, __nv_bfloat16* __restrict__ whl,
                              __nv_bfloat16* __restrict__ wqvh, __nv_bfloat16* __restrict__ wqvl) {
    int i = blockIdx.x * 256 + threadIdx.x;
    if (i < 2 * GH * KP1) {
        int z = i / (GH * KP1); int rem = i - z * (GH * KP1);
        int j = rem / KP1, k = rem - j * KP1;
        const float* src = z ? hWb : hWf;
        float v = (k < 300) ? src[j * 300 + k] : 0.f;
        __nv_bfloat16 h = __float2bfloat16(v);
        whh[i] = h; whl[i] = __float2bfloat16(v - __bfloat162float(h));
    }
    if (i < 2 * HH2 * HH2) {
        const float* src = (i >> 16) ? Wv : Wq;
        float v = src[i & 65535];
        __nv_bfloat16 h = __float2bfloat16(v);
        wqvh[i] = h; wqvl[i] = __float2bfloat16(v - __bfloat162float(h));
    }
}

// =====================================================================
// Tensor GEMM via mma.sync bf16 3-pass hi/lo:
// C[r][j] = bias[j] + sum_k A[row(r)][k] * W[j][k]
// Tile 128x128, K chunks of 64, cp.async double buffer, swizzled ldmatrix.
// blockIdx.z selects weight/output set. MODE1 = hier segment row remap.
// =====================================================================
#define LOAD_CHUNK(cc, st_u32) do { \
    for (int idx = tid; idx < 1024; idx += 256) { \
        int row_ = idx >> 3, kg_ = idx & 7; \
        uint32_t sw_ = SWZ((uint32_t)(row_ * 128 + kg_ * 16)); \
        int r_ = r0 + row_, arow_ = r_; \
        if (MODE) { int m_ = r_ >> 12, n2_ = r_ & 4095; arow_ = (((n2_ & 63) << 4) + m_) * 64 + (n2_ >> 6); } \
        long ko_ = (long)arow_ * KPv + (cc) * 64 + kg_ * 8; \
        long wo_ = (long)(j0 + row_) * KPv + (cc) * 64 + kg_ * 8; \
        cp16((st_u32) + sw_,         Ahi + ko_); \
        cp16((st_u32) + 16384 + sw_, Alo + ko_); \
        cp16((st_u32) + 32768 + sw_, Wh + wo_); \
        cp16((st_u32) + 49152 + sw_, Wl + wo_); \
    } \
    asm volatile("cp.async.commit_group;" ::: "memory"); \
} while (0)

__global__ __launch_bounds__(256, 1)
void tgemm_kernel(const __nv_bfloat16* __restrict__ Ahi, const __nv_bfloat16* __restrict__ Alo,
                  const __nv_bfloat16* __restrict__ Whi, const __nv_bfloat16* __restrict__ Wlo,
                  const float* __restrict__ b0, const float* __restrict__ b1,
                  float* __restrict__ C0, float* __restrict__ C1,
                  int KPv, int J, int MODE) {
    extern __shared__ char dsm[];
    const int tid = threadIdx.x;
    const int warp = tid >> 5, lane = tid & 31;
    const int wm = warp >> 1, wn = warp & 1;       // 4x2 warp grid, warp tile 32x64
    const int r0 = blockIdx.y * 128, j0 = blockIdx.x * 128, z = blockIdx.z;
    const __nv_bfloat16* Wh = Whi + (size_t)z * J * KPv;
    const __nv_bfloat16* Wl = Wlo + (size_t)z * J * KPv;
    const float* bias = z ? b1 : b0;
    float* C = z ? C1 : C0;
    const int NC = KPv >> 6;

    const uint32_t sb = smem_u32_of(dsm);
    float* bs = (float*)(dsm + 131072);
    if (tid < 128) bs[tid] = bias[j0 + tid];

    float acc[2][8][4];
#pragma unroll
    for (int mi = 0; mi < 2; mi++)
#pragma unroll
        for (int ni = 0; ni < 8; ni++)
#pragma unroll
            for (int q = 0; q < 4; q++) acc[mi][ni][q] = 0.f;

    LOAD_CHUNK(0, sb);
    for (int c = 0; c < NC; c++) {
        const uint32_t st = sb + (c & 1) * 65536;
        if (c + 1 < NC) {
            LOAD_CHUNK(c + 1, sb + ((c + 1) & 1) * 65536);
            asm volatile("cp.async.wait_group 1;" ::: "memory");
        } else {
            asm volatile("cp.async.wait_group 0;" ::: "memory");
        }
        __syncthreads();
        // compute chunk c (4 k-atoms of 16)
        const uint32_t arow_l = (lane & 15);
        const uint32_t akb_l  = (lane >> 4) * 8;
        const uint32_t brow_l = (lane & 7) + ((lane >> 4) << 3);
        const uint32_t bkb_l  = ((lane >> 3) & 1) * 8;
#pragma unroll
        for (int ka = 0; ka < 4; ka++) {
            uint32_t ah[2][4], al[2][4];
#pragma unroll
            for (int mi = 0; mi < 2; mi++) {
                uint32_t off = SWZ((wm * 32 + mi * 16 + arow_l) * 128 + (ka * 16 + akb_l) * 2);
                ldm4(ah[mi], st + off);
                ldm4(al[mi], st + 16384 + off);
            }
            uint32_t bh[4][4], bl[4][4];
#pragma unroll
            for (int nb = 0; nb < 4; nb++) {
                uint32_t off = SWZ((wn * 64 + nb * 16 + brow_l) * 128 + (ka * 16 + bkb_l) * 2);
                ldm4(bh[nb], st + 32768 + off);
                ldm4(bl[nb], st + 49152 + off);
            }
#pragma unroll
            for (int mi = 0; mi < 2; mi++)
#pragma unroll
                for (int ni = 0; ni < 8; ni++) {
                    const uint32_t* bh2 = &bh[ni >> 1][(ni & 1) * 2];
                    const uint32_t* bl2 = &bl[ni >> 1][(ni & 1) * 2];
                    mma16816(acc[mi][ni], ah[mi], bh2);
                    mma16816(acc[mi][ni], ah[mi], bl2);
                    mma16816(acc[mi][ni], al[mi], bh2);
                }
        }
        __syncthreads();
    }
    // epilogue: direct stores with bias
#pragma unroll
    for (int mi = 0; mi < 2; mi++) {
#pragma unroll
        for (int ni = 0; ni < 8; ni++) {
            int row = r0 + wm * 32 + mi * 16 + (lane >> 2);
            int cloc = wn * 64 + ni * 8 + (lane & 3) * 2;
            int col = j0 + cloc;
            float bb0 = bs[cloc], bb1 = bs[cloc + 1];
            float2 v0 = make_float2(acc[mi][ni][0] + bb0, acc[mi][ni][1] + bb1);
            float2 v1 = make_float2(acc[mi][ni][2] + bb0, acc[mi][ni][3] + bb1);
            *(float2*)(C + (long)row * J + col) = v0;
            *(float2*)(C + (long)(row + 8) * J + col) = v1;
        }
    }
}

// =====================================================================
// Main GRU recurrence with FUSED input-gate computation (Wih·x inline).
// 128 blocks = (dir 2) x (batch 64), 480 threads.
// Whh: cols 0..63 smem (pitch 68), cols 64..149 reg pairs. Wih in smem.
// =====================================================================
__global__ __launch_bounds__(480, 1)
void main_gru_kernel(const float* __restrict__ sent,
                     const float* __restrict__ mWih_f, const float* __restrict__ mWih_b,
                     const float* __restrict__ mbih_f, const float* __restrict__ mbih_b,
                     const float* __restrict__ Whh_f, const float* __restrict__ Whh_b,
                     const float* __restrict__ bhh_f, const float* __restrict__ bhh_b,
                     float* __restrict__ rnn,
                     __nv_bfloat16* __restrict__ rhi, __nv_bfloat16* __restrict__ rlo) {
    extern __shared__ __align__(16) float sm[];
    float* Ws    = sm;                  // 450*68
    float* Wih_s = Ws + 450 * 68;       // 450*18
    float* h_s   = Wih_s + 450 * 18;    // 160
    float* gh_s  = h_s + 160;           // 456
    float* gin_s = gh_s + 456;          // 152
    float* x_s   = gin_s + 152;         // 20

    const int tid = threadIdx.x;
    const int dir = blockIdx.x >> 6, b = blockIdx.x & 63;
    const float* Whh = dir ? Whh_b : Whh_f;
    const float* bhh = dir ? bhh_b : bhh_f;
    const float* Wih = dir ? mWih_b : mWih_f;
    const float* bih = dir ? mbih_b : mbih_f;

    for (int i = tid; i < 450 * 64; i += 480) {
        int g2 = i >> 6, k = i & 63;
        Ws[g2 * 68 + k] = Whh[g2 * 150 + k];
    }
    for (int i = tid; i < 450 * 17; i += 480) {
        int g2 = i / 17, k = i - g2 * 17;
        Wih_s[g2 * 18 + k] = Wih[g2 * 17 + k];
    }
    const int g = tid;
    u64 wp[43];
    float bh = 0.f, bi_n = 0.f;
    if (g < 450) {
        bh = bhh[g] + ((g < 300) ? bih[g] : 0.f);
        if (g >= 300) bi_n = bih[g];
#pragma unroll
        for (int i = 0; i < 43; i++) wp[i] = *(const u64*)&Whh[g * 150 + 64 + 2 * i];
    }
    for (int i = tid; i < 160; i += 480) h_s[i] = 0.f;
    if (tid < DIN) x_s[tid] = sent[((long)(dir ? (TT - 1) : 0) * 64 + b) * DIN + tid];
    __syncthreads();

    for (int step = 0; step < TT; step++) {
        const int t = dir ? (TT - 1 - step) : step;
        if (g < 450) {
            float gix = 0.f;
#pragma unroll
            for (int k = 0; k < DIN; k++) gix += Wih_s[g * 18 + k] * x_s[k];
            u64 accp = 0ull;
#pragma unroll
            for (int k = 0; k < 64; k += 4) {
                double2 w2 = *(const double2*)&Ws[g * 68 + k];
                double2 h2 = *(const double2*)&h_s[k];
                FMA2(accp, d2u_lo(w2), d2u_lo(h2));
                FMA2(accp, d2u_hi(w2), d2u_hi(h2));
            }
#pragma unroll
            for (int q2 = 0; q2 < 21; q2++) {
                double2 h2 = *(const double2*)&h_s[64 + 4 * q2];
                FMA2(accp, wp[2 * q2], d2u_lo(h2));
                FMA2(accp, wp[2 * q2 + 1], d2u_hi(h2));
            }
            { u64 hl = *(const u64*)&h_s[148]; FMA2(accp, wp[42], hl); }
            float gh = pair_lo(accp) + pair_hi(accp) + bh;
            if (g < 300) gh += gix;
            else gin_s[g - 300] = gix + bi_n;
            gh_s[g] = gh;
        }
        __syncthreads();
        if (g < 150) {
            float r = 1.f / (1.f + expf(-gh_s[g]));
            float z = 1.f / (1.f + expf(-gh_s[150 + g]));
            float n = tanhf(gin_s[g] + r * gh_s[300 + g]);
            float hn = (1.f - z) * n + z * h_s[g];
            h_s[g] = hn;
            long ro = (long)t * 64 + b;
            rnn[ro * 300 + dir * 150 + g] = hn;
            __nv_bfloat16 hh = __float2bfloat16(hn);
            rhi[ro * KP1 + dir * 150 + g] = hh;
            rlo[ro * KP1 + dir * 150 + g] = __float2bfloat16(hn - __bfloat162float(hh));
        } else if (g >= 450 && g < 450 + DIN && step + 1 < TT) {
            int tn = dir ? (TT - 2 - step) : (step + 1);
            x_s[g - 450] = sent[((long)tn * 64 + b) * DIN + (g - 450)];
        }
        __syncthreads();
    }
}

// =====================================================================
// Hier GRU (+ bf16 hi/lo output)
// =====================================================================
#define HPITCH 132
__global__ __launch_bounds__(384, 1)
void hier_gru_kernel(const float* __restrict__ gi_f, const float* __restrict__ gi_b,
                     const float* __restrict__ Whh_f, const float* __restrict__ Whh_b,
                     const float* __restrict__ bhh_f, const float* __restrict__ bhh_b,
                     float* __restrict__ hier,
                     __nv_bfloat16* __restrict__ hhi, __nv_bfloat16* __restrict__ hlo) {
    extern __shared__ __align__(16) float sm[];
    float* Ws = sm;
    float* h_s = Ws + 384 * HPITCH;
    float* gh_s = h_s + 8 * 128;

    const int tid = threadIdx.x;
    const int dir = blockIdx.x >> 9;
    const int n2base = (blockIdx.x & 511) * 8;
    const float* Whh = dir ? Whh_b : Whh_f;
    const float* bhh = dir ? bhh_b : bhh_f;
    const float* gi  = dir ? gi_b  : gi_f;

    for (int i = tid; i < 384 * 128; i += 384) {
        int gg = i >> 7, k = i & 127;
        Ws[gg * HPITCH + k] = Whh[gg * 128 + k];
    }
    for (int i = tid; i < 8 * 128; i += 384) h_s[i] = 0.f;
    const int g = tid;
    const float bh = bhh[g];
    __syncthreads();

    for (int step = 0; step < MSL; step++) {
        const int m = dir ? (MSL - 1 - step) : step;
        float pg[3][3];
#pragma unroll
        for (int ii = 0; ii < 3; ii++) {
            int idx = tid + ii * 384;
            if (idx < 1024) {
                int c = idx >> 7, j = idx & 127;
                long gb = ((long)m * NSEG + (n2base + c)) * GH;
                pg[ii][0] = gi[gb + j]; pg[ii][1] = gi[gb + 128 + j]; pg[ii][2] = gi[gb + 256 + j];
            }
        }
        u64 accp[8];
#pragma unroll
        for (int c = 0; c < 8; c++) accp[c] = 0ull;
#pragma unroll 8
        for (int k = 0; k < 128; k += 4) {
            double2 w2 = *(const double2*)&Ws[g * HPITCH + k];
            u64 wlo = d2u_lo(w2), whi = d2u_hi(w2);
#pragma unroll
            for (int c = 0; c < 8; c++) {
                double2 h2 = *(const double2*)&h_s[c * 128 + k];
                FMA2(accp[c], wlo, d2u_lo(h2));
                FMA2(accp[c], whi, d2u_hi(h2));
            }
        }
#pragma unroll
        for (int c = 0; c < 8; c++)
            gh_s[c * 384 + g] = pair_lo(accp[c]) + pair_hi(accp[c]) + bh;
        __syncthreads();
#pragma unroll
        for (int ii = 0; ii < 3; ii++) {
            int idx = tid + ii * 384;
            if (idx < 1024) {
                int c = idx >> 7, j = idx & 127;
                float r = 1.f / (1.f + expf(-(pg[ii][0] + gh_s[c * 384 + j])));
                float z = 1.f / (1.f + expf(-(pg[ii][1] + gh_s[c * 384 + 128 + j])));
                float n = tanhf(pg[ii][2] + r * gh_s[c * 384 + 256 + j]);
                float hn = (1.f - z) * n + z * h_s[c * 128 + j];
                h_s[c * 128 + j] = hn;
                long ro = (long)m * NSEG + (n2base + c);
                hier[ro * HH2 + dir * 128 + j] = hn;
                __nv_bfloat16 hh = __float2bfloat16(hn);
                hhi[ro * HH2 + dir * 128 + j] = hh;
                hlo[ro * HH2 + dir * 128 + j] = __float2bfloat16(hn - __bfloat162float(hh));
            }
        }
        __syncthreads();
    }
}

// =====================================================================
// Attention per segment.
// =====================================================================
#define APITCH 261
__global__ __launch_bounds__(256)
void attn_kernel(const float* __restrict__ q, const float* __restrict__ v,
                 const float* __restrict__ hv, float* __restrict__ ctx) {
    extern __shared__ float smA[];
    float* qs = smA;
    float* vs = qs + 16 * APITCH;
    float* hs = vs + 16 * APITCH;
    float* ss = hs + 16 * APITCH;
    float* ws = ss + 16 * 17;
    const int tid = threadIdx.x, n2 = blockIdx.x;

    for (int i = tid; i < 16 * 256; i += 256) {
        int m = i >> 8, d = i & 255;
        long src = ((long)m * NSEG + n2) * HH2 + d;
        qs[m * APITCH + d] = q[src];
        vs[m * APITCH + d] = v[src];
        hs[m * APITCH + d] = hv[src];
    }
    __syncthreads();
    {
        int l = tid >> 4, mm = tid & 15;
        float acc = 0.f;
#pragma unroll 8
        for (int k = 0; k < 256; k++) acc += qs[l * APITCH + k] * vs[mm * APITCH + k];
        ss[l * 17 + mm] = acc;
    }
    __syncthreads();
    if (tid < 16) {
        int l = tid;
        float mx = -1e30f;
#pragma unroll
        for (int mm = 0; mm < 16; mm++) mx = fmaxf(mx, ss[l * 17 + mm]);
        float s = 0.f, e[16];
#pragma unroll
        for (int mm = 0; mm < 16; mm++) { e[mm] = expf(ss[l * 17 + mm] - mx); s += e[mm]; }
        float inv = 1.f / s;
#pragma unroll
        for (int mm = 0; mm < 16; mm++) ss[l * 17 + mm] = e[mm] * inv;
    }
    __syncthreads();
    if (tid < 16) {
        float s = 0.f;
#pragma unroll
        for (int l = 0; l < 16; l++) s += ss[l * 17 + tid];
        ws[tid] = s;
    }
    __syncthreads();
    {
        float acc = 0.f;
#pragma unroll
        for (int mm = 0; mm < 16; mm++) acc += ws[mm] * hs[mm * APITCH + tid];
        ctx[(long)n2 * HH2 + tid] = acc;
    }
}

// =====================================================================
// Fused logits + masked CE.
// =====================================================================
__global__ __launch_bounds__(256, 1)
void ce_kernel(const float* __restrict__ rnn, const float* __restrict__ ctx,
               const float* __restrict__ Wp, const float* __restrict__ bp,
               const float* __restrict__ Wk, const float* __restrict__ bk,
               const int* __restrict__ pitches, const int* __restrict__ kss,
               float* __restrict__ part) {
    extern __shared__ __align__(16) float smC[];
    float* Wps = smC;
    float* Wks = Wps + NP * 556;
    float* bps = Wks + NK * 256;
    float* bks = bps + NP;
    float* red = bks + NK;

    const int tid = threadIdx.x;
    for (int i = tid; i < NP * 556; i += 256) Wps[i] = Wp[i];
    for (int i = tid; i < NK * 256; i += 256) Wks[i] = Wk[i];
    if (tid < NP) bps[tid] = bp[tid];
    if (tid < NK) bks[tid] = bk[tid];
    __syncthreads();

    const int row = blockIdx.x * 256 + tid;
    const int t = row >> 6, b = row & 63;
    const float* xr = rnn + (long)row * 300;
    const float* xc = ctx + ((long)(b * 64 + (t >> 4))) * HH2;

    float lg[NP], lgk[NK];
#pragma unroll
    for (int c = 0; c < NP; c++) lg[c] = bps[c];
#pragma unroll
    for (int c = 0; c < NK; c++) lgk[c] = bks[c];

    for (int k4 = 0; k4 < 75; k4++) {
        float4 x = *(const float4*)&xr[k4 * 4];
#pragma unroll
        for (int c = 0; c < NP; c++) {
            const float* wr = &Wps[c * 556 + k4 * 4];
            lg[c] += wr[0] * x.x + wr[1] * x.y + wr[2] * x.z + wr[3] * x.w;
        }
    }
    for (int k4 = 0; k4 < 64; k4++) {
        float4 x = *(const float4*)&xc[k4 * 4];
#pragma unroll
        for (int c = 0; c < NP; c++) {
            const float* wr = &Wps[c * 556 + 300 + k4 * 4];
            lg[c] += wr[0] * x.x + wr[1] * x.y + wr[2] * x.z + wr[3] * x.w;
        }
#pragma unroll
        for (int c = 0; c < NK; c++) {
            const float* wr = &Wks[c * 256 + k4 * 4];
            lgk[c] += wr[0] * x.x + wr[1] * x.y + wr[2] * x.z + wr[3] * x.w;
        }
    }

    int tp = pitches[row];
    float mx = -1e30f;
#pragma unroll
    for (int c = 0; c < NP; c++) mx = fmaxf(mx, lg[c]);
    float s = 0.f;
#pragma unroll
    for (int c = 0; c < NP; c++) s += expf(lg[c] - mx);
    float lsel = 0.f;
#pragma unroll
    for (int c = 0; c < NP; c++) lsel += (c == tp) ? lg[c] : 0.f;
    float nllp = 0.f, cp = 0.f;
    if (tp != 34) { nllp = (logf(s) + mx) - lsel; cp = 1.f; }

    int tk = kss[row];
    float mxk = -1e30f;
#pragma unroll
    for (int c = 0; c < NK; c++) mxk = fmaxf(mxk, lgk[c]);
    float sk = 0.f;
#pragma unroll
    for (int c = 0; c < NK; c++) sk += expf(lgk[c] - mxk);
    float ksel = 0.f;
#pragma unroll
    for (int c = 0; c < NK; c++) ksel += (c == tk) ? lgk[c] : 0.f;
    float nllk = 0.f, ck = 0.f;
    if (tk != 14) { nllk = (logf(sk) + mxk) - ksel; ck = 1.f; }

    red[tid] = nllp; red[256 + tid] = cp; red[512 + tid] = nllk; red[768 + tid] = ck;
    __syncthreads();
    for (int off = 128; off > 0; off >>= 1) {
        if (tid < off) {
            red[tid] += red[tid + off];
            red[256 + tid] += red[256 + tid + off];
            red[512 + tid] += red[512 + tid + off];
            red[768 + tid] += red[768 + tid + off];
        }
        __syncthreads();
    }
    if (tid == 0) {
        part[blockIdx.x * 4 + 0] = red[0];
        part[blockIdx.x * 4 + 1] = red[256];
        part[blockIdx.x * 4 + 2] = red[512];
        part[blockIdx.x * 4 + 3] = red[768];
    }
}

__global__ __launch_bounds__(256)
void final_kernel(const float* __restrict__ part, float* __restrict__ out) {
    __shared__ float s0[256], s1[256], s2[256], s3[256];
    const int tid = threadIdx.x;
    s0[tid] = part[tid * 4 + 0]; s1[tid] = part[tid * 4 + 1];
    s2[tid] = part[tid * 4 + 2]; s3[tid] = part[tid * 4 + 3];
    __syncthreads();
    for (int off = 128; off > 0; off >>= 1) {
        if (tid < off) {
            s0[tid] += s0[tid + off]; s1[tid] += s1[tid + off];
            s2[tid] += s2[tid + off]; s3[tid] += s3[tid + off];
        }
        __syncthreads();
    }
    if (tid == 0) out[0] = s0[0] / fmaxf(s1[0], 1.f) + s2[0] / fmaxf(s3[0], 1.f);
}

// =====================================================================
// host
// =====================================================================
extern "C" void kernel_launch(void* const* d_in, const int* in_sizes, int n_in,
                              void* d_out, int out_size) {
    const float* sentences = (const float*)d_in[0];
    const int* pitches = (const int*)d_in[1];
    const int* kss = (const int*)d_in[2];
    const float* mWih_f = (const float*)d_in[5];
    const float* mWhh_f = (const float*)d_in[6];
    const float* mbih_f = (const float*)d_in[7];
    const float* mbhh_f = (const float*)d_in[8];
    const float* mWih_b = (const float*)d_in[9];
    const float* mWhh_b = (const float*)d_in[10];
    const float* mbih_b = (const float*)d_in[11];
    const float* mbhh_b = (const float*)d_in[12];
    const float* hWih_f = (const float*)d_in[13];
    const float* hWhh_f = (const float*)d_in[14];
    const float* hbih_f = (const float*)d_in[15];
    const float* hbhh_f = (const float*)d_in[16];
    const float* hWih_b = (const float*)d_in[17];
    const float* hWhh_b = (const float*)d_in[18];
    const float* hbih_b = (const float*)d_in[19];
    const float* hbhh_b = (const float*)d_in[20];
    const float* Wq = (const float*)d_in[21];
    const float* bq = (const float*)d_in[22];
    const float* Wv = (const float*)d_in[23];
    const float* bv = (const float*)d_in[24];
    const float* Wp = (const float*)d_in[25];
    const float* bp = (const float*)d_in[26];
    const float* Wk = (const float*)d_in[27];
    const float* bk = (const float*)d_in[28];
    float* out = (float*)d_out;

    float *p_rnn, *p_gi_hf, *p_gi_hb, *p_hier, *p_q, *p_v, *p_ctx, *p_part;
    __nv_bfloat16 *p_rhi, *p_rlo, *p_hhi, *p_hlo, *p_whh, *p_whl, *p_qvh, *p_qvl;
    cudaGetSymbolAddress((void**)&p_rnn, g_rnn);
    cudaGetSymbolAddress((void**)&p_gi_hf, g_gi_hf);
    cudaGetSymbolAddress((void**)&p_gi_hb, g_gi_hb);
    cudaGetSymbolAddress((void**)&p_hier, g_hier);
    cudaGetSymbolAddress((void**)&p_q, g_q);
    cudaGetSymbolAddress((void**)&p_v, g_v);
    cudaGetSymbolAddress((void**)&p_ctx, g_ctx);
    cudaGetSymbolAddress((void**)&p_part, g_part);
    cudaGetSymbolAddress((void**)&p_rhi, g_rnn_hi);
    cudaGetSymbolAddress((void**)&p_rlo, g_rnn_lo);
    cudaGetSymbolAddress((void**)&p_hhi, g_hier_hi);
    cudaGetSymbolAddress((void**)&p_hlo, g_hier_lo);
    cudaGetSymbolAddress((void**)&p_whh, g_wh_hi);
    cudaGetSymbolAddress((void**)&p_whl, g_wh_lo);
    cudaGetSymbolAddress((void**)&p_qvh, g_wqv_hi);
    cudaGetSymbolAddress((void**)&p_qvl, g_wqv_lo);

    const int SM_MAIN = (450 * 68 + 450 * 18 + 160 + 456 + 152 + 20) * 4;
    const int SM_HIER = (384 * HPITCH + 8 * 128 + 8 * 384) * 4;
    const int SM_ATTN = (3 * 16 * APITCH + 16 * 17 + 16) * 4;
    const int SM_CE   = (NP * 556 + NK * 256 + NP + NK + 1024) * 4;
    const int SM_TG   = 2 * 65536 + 512;
    cudaFuncSetAttribute(main_gru_kernel, cudaFuncAttributeMaxDynamicSharedMemorySize, SM_MAIN);
    cudaFuncSetAttribute(hier_gru_kernel, cudaFuncAttributeMaxDynamicSharedMemorySize, SM_HIER);
    cudaFuncSetAttribute(attn_kernel, cudaFuncAttributeMaxDynamicSharedMemorySize, SM_ATTN);
    cudaFuncSetAttribute(ce_kernel, cudaFuncAttributeMaxDynamicSharedMemorySize, SM_CE);
    cudaFuncSetAttribute(tgemm_kernel, cudaFuncAttributeMaxDynamicSharedMemorySize, SM_TG);

    conv_w_kernel<<<960, 256>>>(hWih_f, hWih_b, Wq, Wv, p_whh, p_whl, p_qvh, p_qvl);
    main_gru_kernel<<<128, 480, SM_MAIN>>>(sentences, mWih_f, mWih_b, mbih_f, mbih_b,
                                           mWhh_f, mWhh_b, mbhh_f, mbhh_b,
                                           p_rnn, p_rhi, p_rlo);
    // hier input gates: [65536,320] x [320,384]^T (fwd/bwd via z)
    tgemm_kernel<<<dim3(3, 512, 2), 256, SM_TG>>>(p_rhi, p_rlo, p_whh, p_whl,
                                                  hbih_f, hbih_b, p_gi_hf, p_gi_hb, KP1, GH, 1);
    hier_gru_kernel<<<1024, 384, SM_HIER>>>(p_gi_hf, p_gi_hb, hWhh_f, hWhh_b, hbhh_f, hbhh_b,
                                            p_hier, p_hhi, p_hlo);
    // q/v: [65536,256] x [256,256]^T (q/v via z)
    tgemm_kernel<<<dim3(2, 512, 2), 256, SM_TG>>>(p_hhi, p_hlo, p_qvh, p_qvl,
                                                  bq, bv, p_q, p_v, HH2, HH2, 0);
    attn_kernel<<<NSEG, 256, SM_ATTN>>>(p_q, p_v, p_hier, p_ctx);
    ce_kernel<<<NROW / 256, 256, SM_CE>>>(p_rnn, p_ctx, Wp, bp, Wk, bk, pitches, kss, p_part);
    final_kernel<<<1, 256>>>(p_part, out);
}

// round 15
// speedup vs baseline: 1.3173x; 1.0392x over previous
#include <cuda_runtime.h>
#include <cuda_bf16.h>
#include <math.h>
#include <stdint.h>

#define TT 1024
#define BB 64
#define DIN 17
#define HM 150
#define GM 450
#define GH 384
#define MSL 16
#define NSEG 4096
#define HH2 256
#define NP 35
#define NK 15
#define NROW 65536
#define KP1 320

typedef unsigned long long u64;

#define FMA2(d, a, b) asm("fma.rn.f32x2 %0, %1, %2, %0;" : "+l"(d) : "l"(a), "l"(b))
__device__ __forceinline__ float pair_lo(u64 p) { return __uint_as_float((unsigned)p); }
__device__ __forceinline__ float pair_hi(u64 p) { return __uint_as_float((unsigned)(p >> 32)); }
__device__ __forceinline__ u64 d2u_lo(double2 d) { return (u64)__double_as_longlong(d.x); }
__device__ __forceinline__ u64 d2u_hi(double2 d) { return (u64)__double_as_longlong(d.y); }

// fast activations: __expf-based, rel err ~2^-21 (loss budget 1e-3)
__device__ __forceinline__ float fsig(float x) {
    return __fdividef(1.f, 1.f + __expf(-x));
}
__device__ __forceinline__ float ftanh(float x) {
    // 1 - 2/(e^{2x}+1); overflow-safe (e^inf -> inf -> 1; e^-inf -> 0 -> -1)
    return 1.f - __fdividef(2.f, __expf(2.f * x) + 1.f);
}

__device__ __forceinline__ uint32_t smem_u32_of(const void* p) {
    uint32_t a;
    asm("{ .reg .u64 t; cvta.to.shared.u64 t, %1; cvt.u32.u64 %0, t; }" : "=r"(a) : "l"(p));
    return a;
}
#define SWZ(b) ((b) ^ (((b) >> 3) & 0x70))

__device__ __forceinline__ void cp16(uint32_t dst, const void* src) {
    asm volatile("cp.async.cg.shared.global [%0], [%1], 16;" :: "r"(dst), "l"(src) : "memory");
}
__device__ __forceinline__ void ldm4(uint32_t* r, uint32_t addr) {
    asm volatile("ldmatrix.sync.aligned.m8n8.x4.shared.b16 {%0,%1,%2,%3}, [%4];"
                 : "=r"(r[0]), "=r"(r[1]), "=r"(r[2]), "=r"(r[3]) : "r"(addr));
}
__device__ __forceinline__ void mma16816(float* d, const uint32_t* a, const uint32_t* b) {
    asm volatile("mma.sync.aligned.m16n8k16.row.col.f32.bf16.bf16.f32 "
                 "{%0,%1,%2,%3}, {%4,%5,%6,%7}, {%8,%9}, {%0,%1,%2,%3};"
                 : "+f"(d[0]), "+f"(d[1]), "+f"(d[2]), "+f"(d[3])
                 : "r"(a[0]), "r"(a[1]), "r"(a[2]), "r"(a[3]), "r"(b[0]), "r"(b[1]));
}

// ---------------- scratch ----------------
__device__ float g_rnn [NROW * 300];
__device__ float g_gi_hf[NROW * GH];
__device__ float g_gi_hb[NROW * GH];
__device__ float g_hier[NROW * HH2];
__device__ float g_q   [NROW * HH2];
__device__ float g_v   [NROW * HH2];
__device__ float g_ctx [NSEG * HH2];
__device__ float g_part[256 * 4];
__device__ __nv_bfloat16 g_rnn_hi[NROW * KP1];
__device__ __nv_bfloat16 g_rnn_lo[NROW * KP1];
__device__ __nv_bfloat16 g_hier_hi[NROW * HH2];
__device__ __nv_bfloat16 g_hier_lo[NROW * HH2];
__device__ __nv_bfloat16 g_wh_hi[2 * GH * KP1];
__device__ __nv_bfloat16 g_wh_lo[2 * GH * KP1];
__device__ __nv_bfloat16 g_wqv_hi[2 * HH2 * HH2];
__device__ __nv_bfloat16 g_wqv_lo[2 * HH2 * HH2];

// ---------------- weight hi/lo split ----------------
__global__ void conv_w_kernel(const float* __restrict__ hWf, const float* __restrict__ hWb,
                              const float* __restrict__ Wq, const float* __restrict__ Wv,
                              __nv_bfloat16* __restrict__ whh, __nv_bfloat16* __restrict__ whl,
                              __nv_bfloat16* __restrict__ wqvh, __nv_bfloat16* __restrict__ wqvl) {
    int i = blockIdx.x * 256 + threadIdx.x;
    if (i < 2 * GH * KP1) {
        int z = i / (GH * KP1); int rem = i - z * (GH * KP1);
        int j = rem / KP1, k = rem - j * KP1;
        const float* src = z ? hWb : hWf;
        float v = (k < 300) ? src[j * 300 + k] : 0.f;
        __nv_bfloat16 h = __float2bfloat16(v);
        whh[i] = h; whl[i] = __float2bfloat16(v - __bfloat162float(h));
    }
    if (i < 2 * HH2 * HH2) {
        const float* src = (i >> 16) ? Wv : Wq;
        float v = src[i & 65535];
        __nv_bfloat16 h = __float2bfloat16(v);
        wqvh[i] = h; wqvl[i] = __float2bfloat16(v - __bfloat162float(h));
    }
}

// =====================================================================
// Tensor GEMM via mma.sync bf16 3-pass hi/lo (unchanged from R14).
// =====================================================================
#define LOAD_CHUNK(cc, st_u32) do { \
    for (int idx = tid; idx < 1024; idx += 256) { \
        int row_ = idx >> 3, kg_ = idx & 7; \
        uint32_t sw_ = SWZ((uint32_t)(row_ * 128 + kg_ * 16)); \
        int r_ = r0 + row_, arow_ = r_; \
        if (MODE) { int m_ = r_ >> 12, n2_ = r_ & 4095; arow_ = (((n2_ & 63) << 4) + m_) * 64 + (n2_ >> 6); } \
        long ko_ = (long)arow_ * KPv + (cc) * 64 + kg_ * 8; \
        long wo_ = (long)(j0 + row_) * KPv + (cc) * 64 + kg_ * 8; \
        cp16((st_u32) + sw_,         Ahi + ko_); \
        cp16((st_u32) + 16384 + sw_, Alo + ko_); \
        cp16((st_u32) + 32768 + sw_, Wh + wo_); \
        cp16((st_u32) + 49152 + sw_, Wl + wo_); \
    } \
    asm volatile("cp.async.commit_group;" ::: "memory"); \
} while (0)

__global__ __launch_bounds__(256, 1)
void tgemm_kernel(const __nv_bfloat16* __restrict__ Ahi, const __nv_bfloat16* __restrict__ Alo,
                  const __nv_bfloat16* __restrict__ Whi, const __nv_bfloat16* __restrict__ Wlo,
                  const float* __restrict__ b0, const float* __restrict__ b1,
                  float* __restrict__ C0, float* __restrict__ C1,
                  int KPv, int J, int MODE) {
    extern __shared__ char dsm[];
    const int tid = threadIdx.x;
    const int warp = tid >> 5, lane = tid & 31;
    const int wm = warp >> 1, wn = warp & 1;
    const int r0 = blockIdx.y * 128, j0 = blockIdx.x * 128, z = blockIdx.z;
    const __nv_bfloat16* Wh = Whi + (size_t)z * J * KPv;
    const __nv_bfloat16* Wl = Wlo + (size_t)z * J * KPv;
    const float* bias = z ? b1 : b0;
    float* C = z ? C1 : C0;
    const int NC = KPv >> 6;

    const uint32_t sb = smem_u32_of(dsm);
    float* bs = (float*)(dsm + 131072);
    if (tid < 128) bs[tid] = bias[j0 + tid];

    float acc[2][8][4];
#pragma unroll
    for (int mi = 0; mi < 2; mi++)
#pragma unroll
        for (int ni = 0; ni < 8; ni++)
#pragma unroll
            for (int q = 0; q < 4; q++) acc[mi][ni][q] = 0.f;

    LOAD_CHUNK(0, sb);
    for (int c = 0; c < NC; c++) {
        const uint32_t st = sb + (c & 1) * 65536;
        if (c + 1 < NC) {
            LOAD_CHUNK(c + 1, sb + ((c + 1) & 1) * 65536);
            asm volatile("cp.async.wait_group 1;" ::: "memory");
        } else {
            asm volatile("cp.async.wait_group 0;" ::: "memory");
        }
        __syncthreads();
        const uint32_t arow_l = (lane & 15);
        const uint32_t akb_l  = (lane >> 4) * 8;
        const uint32_t brow_l = (lane & 7) + ((lane >> 4) << 3);
        const uint32_t bkb_l  = ((lane >> 3) & 1) * 8;
#pragma unroll
        for (int ka = 0; ka < 4; ka++) {
            uint32_t ah[2][4], al[2][4];
#pragma unroll
            for (int mi = 0; mi < 2; mi++) {
                uint32_t off = SWZ((wm * 32 + mi * 16 + arow_l) * 128 + (ka * 16 + akb_l) * 2);
                ldm4(ah[mi], st + off);
                ldm4(al[mi], st + 16384 + off);
            }
            uint32_t bh[4][4], bl[4][4];
#pragma unroll
            for (int nb = 0; nb < 4; nb++) {
                uint32_t off = SWZ((wn * 64 + nb * 16 + brow_l) * 128 + (ka * 16 + bkb_l) * 2);
                ldm4(bh[nb], st + 32768 + off);
                ldm4(bl[nb], st + 49152 + off);
            }
#pragma unroll
            for (int mi = 0; mi < 2; mi++)
#pragma unroll
                for (int ni = 0; ni < 8; ni++) {
                    const uint32_t* bh2 = &bh[ni >> 1][(ni & 1) * 2];
                    const uint32_t* bl2 = &bl[ni >> 1][(ni & 1) * 2];
                    mma16816(acc[mi][ni], ah[mi], bh2);
                    mma16816(acc[mi][ni], ah[mi], bl2);
                    mma16816(acc[mi][ni], al[mi], bh2);
                }
        }
        __syncthreads();
    }
#pragma unroll
    for (int mi = 0; mi < 2; mi++) {
#pragma unroll
        for (int ni = 0; ni < 8; ni++) {
            int row = r0 + wm * 32 + mi * 16 + (lane >> 2);
            int cloc = wn * 64 + ni * 8 + (lane & 3) * 2;
            int col = j0 + cloc;
            float bb0 = bs[cloc], bb1 = bs[cloc + 1];
            float2 v0 = make_float2(acc[mi][ni][0] + bb0, acc[mi][ni][1] + bb1);
            float2 v1 = make_float2(acc[mi][ni][2] + bb0, acc[mi][ni][3] + bb1);
            *(float2*)(C + (long)row * J + col) = v0;
            *(float2*)(C + (long)(row + 8) * J + col) = v1;
        }
    }
}

// =====================================================================
// Main GRU recurrence with fused input gates (fast activations, dual acc)
// =====================================================================
__global__ __launch_bounds__(480, 1)
void main_gru_kernel(const float* __restrict__ sent,
                     const float* __restrict__ mWih_f, const float* __restrict__ mWih_b,
                     const float* __restrict__ mbih_f, const float* __restrict__ mbih_b,
                     const float* __restrict__ Whh_f, const float* __restrict__ Whh_b,
                     const float* __restrict__ bhh_f, const float* __restrict__ bhh_b,
                     float* __restrict__ rnn,
                     __nv_bfloat16* __restrict__ rhi, __nv_bfloat16* __restrict__ rlo) {
    extern __shared__ __align__(16) float sm[];
    float* Ws    = sm;                  // 450*68
    float* Wih_s = Ws + 450 * 68;       // 450*18
    float* h_s   = Wih_s + 450 * 18;    // 160
    float* gh_s  = h_s + 160;           // 456
    float* gin_s = gh_s + 456;          // 152
    float* x_s   = gin_s + 152;         // 20

    const int tid = threadIdx.x;
    const int dir = blockIdx.x >> 6, b = blockIdx.x & 63;
    const float* Whh = dir ? Whh_b : Whh_f;
    const float* bhh = dir ? bhh_b : bhh_f;
    const float* Wih = dir ? mWih_b : mWih_f;
    const float* bih = dir ? mbih_b : mbih_f;

    for (int i = tid; i < 450 * 64; i += 480) {
        int g2 = i >> 6, k = i & 63;
        Ws[g2 * 68 + k] = Whh[g2 * 150 + k];
    }
    for (int i = tid; i < 450 * 17; i += 480) {
        int g2 = i / 17, k = i - g2 * 17;
        Wih_s[g2 * 18 + k] = Wih[g2 * 17 + k];
    }
    const int g = tid;
    u64 wp[43];
    float bh = 0.f, bi_n = 0.f;
    if (g < 450) {
        bh = bhh[g] + ((g < 300) ? bih[g] : 0.f);
        if (g >= 300) bi_n = bih[g];
#pragma unroll
        for (int i = 0; i < 43; i++) wp[i] = *(const u64*)&Whh[g * 150 + 64 + 2 * i];
    }
    for (int i = tid; i < 160; i += 480) h_s[i] = 0.f;
    if (tid < DIN) x_s[tid] = sent[((long)(dir ? (TT - 1) : 0) * 64 + b) * DIN + tid];
    __syncthreads();

    for (int step = 0; step < TT; step++) {
        const int t = dir ? (TT - 1 - step) : step;
        if (g < 450) {
            float gix = 0.f;
#pragma unroll
            for (int k = 0; k < DIN; k++) gix += Wih_s[g * 18 + k] * x_s[k];
            u64 acc0 = 0ull, acc1 = 0ull;
#pragma unroll
            for (int k = 0; k < 64; k += 8) {
                double2 w2 = *(const double2*)&Ws[g * 68 + k];
                double2 h2 = *(const double2*)&h_s[k];
                FMA2(acc0, d2u_lo(w2), d2u_lo(h2));
                FMA2(acc1, d2u_hi(w2), d2u_hi(h2));
                double2 w3 = *(const double2*)&Ws[g * 68 + k + 4];
                double2 h3 = *(const double2*)&h_s[k + 4];
                FMA2(acc0, d2u_lo(w3), d2u_lo(h3));
                FMA2(acc1, d2u_hi(w3), d2u_hi(h3));
            }
#pragma unroll
            for (int q2 = 0; q2 < 21; q2++) {
                double2 h2 = *(const double2*)&h_s[64 + 4 * q2];
                FMA2(acc0, wp[2 * q2], d2u_lo(h2));
                FMA2(acc1, wp[2 * q2 + 1], d2u_hi(h2));
            }
            { u64 hl = *(const u64*)&h_s[148]; FMA2(acc0, wp[42], hl); }
            float gh = pair_lo(acc0) + pair_hi(acc0) + pair_lo(acc1) + pair_hi(acc1) + bh;
            if (g < 300) gh += gix;
            else gin_s[g - 300] = gix + bi_n;
            gh_s[g] = gh;
        }
        __syncthreads();
        if (g < 150) {
            float r = fsig(gh_s[g]);
            float z = fsig(gh_s[150 + g]);
            float n = ftanh(gin_s[g] + r * gh_s[300 + g]);
            float hn = (1.f - z) * n + z * h_s[g];
            h_s[g] = hn;
            long ro = (long)t * 64 + b;
            rnn[ro * 300 + dir * 150 + g] = hn;
            __nv_bfloat16 hh = __float2bfloat16(hn);
            rhi[ro * KP1 + dir * 150 + g] = hh;
            rlo[ro * KP1 + dir * 150 + g] = __float2bfloat16(hn - __bfloat162float(hh));
        } else if (g >= 450 && g < 450 + DIN && step + 1 < TT) {
            int tn = dir ? (TT - 2 - step) : (step + 1);
            x_s[g - 450] = sent[((long)tn * 64 + b) * DIN + (g - 450)];
        }
        __syncthreads();
    }
}

// =====================================================================
// Hier GRU v2: 512 blocks = (dir 2) x (256 groups), 16 chains/block,
// 768 threads. Per thread: 2 gates x 4 chains. Weights in float4-slot
// layout W4[kq][gate] (conflict-free), h broadcast.
// smem: W4 196608 + h 8192 + gh 24576 = 229376 B.
// =====================================================================
__global__ __launch_bounds__(768, 1)
void hier_gru_kernel(const float* __restrict__ gi_f, const float* __restrict__ gi_b,
                     const float* __restrict__ Whh_f, const float* __restrict__ Whh_b,
                     const float* __restrict__ bhh_f, const float* __restrict__ bhh_b,
                     float* __restrict__ hier,
                     __nv_bfloat16* __restrict__ hhi, __nv_bfloat16* __restrict__ hlo) {
    extern __shared__ __align__(16) float sm[];
    float* W4   = sm;                    // [32][384] float4 slots = 49152 floats
    float* h_s  = sm + 32 * 384 * 4;     // 16*128
    float* gh_s = h_s + 16 * 128;        // 16*384

    const int tid = threadIdx.x;
    const int dir = blockIdx.x >> 8;
    const int n2base = (blockIdx.x & 255) * 16;
    const float* Whh = dir ? Whh_b : Whh_f;
    const float* bhh = dir ? bhh_b : bhh_f;
    const float* gi  = dir ? gi_b  : gi_f;

    for (int i = tid; i < 384 * 32; i += 768) {
        int gg = i >> 5, kq = i & 31;
        *(float4*)&W4[(kq * 384 + gg) * 4] = *(const float4*)&Whh[gg * 128 + kq * 4];
    }
    for (int i = tid; i < 16 * 128; i += 768) h_s[i] = 0.f;
    const int g2 = tid % 192;        // gates g2 and g2+192
    const int quad = tid / 192;      // chains quad*4 .. quad*4+3
    const float bh0 = bhh[g2], bh1 = bhh[g2 + 192];
    __syncthreads();

    for (int step = 0; step < MSL; step++) {
        const int m = dir ? (MSL - 1 - step) : step;
        // prefetch gi for update slots (16*128 = 2048 slots, 3 per thread max)
        float pg[3][3];
#pragma unroll
        for (int ii = 0; ii < 3; ii++) {
            int idx = tid + ii * 768;
            if (idx < 2048) {
                int c = idx >> 7, j = idx & 127;
                long gb = ((long)m * NSEG + (n2base + c)) * GH;
                pg[ii][0] = gi[gb + j]; pg[ii][1] = gi[gb + 128 + j]; pg[ii][2] = gi[gb + 256 + j];
            }
        }
        // matvec: 2 gates x 4 chains per thread
        u64 acc[2][4];
#pragma unroll
        for (int gi2 = 0; gi2 < 2; gi2++)
#pragma unroll
            for (int ci = 0; ci < 4; ci++) acc[gi2][ci] = 0ull;
#pragma unroll 8
        for (int kq = 0; kq < 32; kq++) {
            double2 wA = *(const double2*)&W4[(kq * 384 + g2) * 4];
            double2 wB = *(const double2*)&W4[(kq * 384 + 192 + g2) * 4];
            u64 wA0 = d2u_lo(wA), wA1 = d2u_hi(wA);
            u64 wB0 = d2u_lo(wB), wB1 = d2u_hi(wB);
#pragma unroll
            for (int ci = 0; ci < 4; ci++) {
                double2 h2 = *(const double2*)&h_s[(quad * 4 + ci) * 128 + kq * 4];
                u64 h0 = d2u_lo(h2), h1 = d2u_hi(h2);
                FMA2(acc[0][ci], wA0, h0);
                FMA2(acc[0][ci], wA1, h1);
                FMA2(acc[1][ci], wB0, h0);
                FMA2(acc[1][ci], wB1, h1);
            }
        }
#pragma unroll
        for (int ci = 0; ci < 4; ci++) {
            int c = quad * 4 + ci;
            gh_s[c * 384 + g2]       = pair_lo(acc[0][ci]) + pair_hi(acc[0][ci]) + bh0;
            gh_s[c * 384 + 192 + g2] = pair_lo(acc[1][ci]) + pair_hi(acc[1][ci]) + bh1;
        }
        __syncthreads();
        // update
#pragma unroll
        for (int ii = 0; ii < 3; ii++) {
            int idx = tid + ii * 768;
            if (idx < 2048) {
                int c = idx >> 7, j = idx & 127;
                float r = fsig(pg[ii][0] + gh_s[c * 384 + j]);
                float z = fsig(pg[ii][1] + gh_s[c * 384 + 128 + j]);
                float n = ftanh(pg[ii][2] + r * gh_s[c * 384 + 256 + j]);
                float hn = (1.f - z) * n + z * h_s[c * 128 + j];
                h_s[c * 128 + j] = hn;
                long ro = (long)m * NSEG + (n2base + c);
                hier[ro * HH2 + dir * 128 + j] = hn;
                __nv_bfloat16 hh = __float2bfloat16(hn);
                hhi[ro * HH2 + dir * 128 + j] = hh;
                hlo[ro * HH2 + dir * 128 + j] = __float2bfloat16(hn - __bfloat162float(hh));
            }
        }
        __syncthreads();
    }
}

// =====================================================================
// Attention per segment.
// =====================================================================
#define APITCH 261
__global__ __launch_bounds__(256)
void attn_kernel(const float* __restrict__ q, const float* __restrict__ v,
                 const float* __restrict__ hv, float* __restrict__ ctx) {
    extern __shared__ float smA[];
    float* qs = smA;
    float* vs = qs + 16 * APITCH;
    float* hs = vs + 16 * APITCH;
    float* ss = hs + 16 * APITCH;
    float* ws = ss + 16 * 17;
    const int tid = threadIdx.x, n2 = blockIdx.x;

    for (int i = tid; i < 16 * 256; i += 256) {
        int m = i >> 8, d = i & 255;
        long src = ((long)m * NSEG + n2) * HH2 + d;
        qs[m * APITCH + d] = q[src];
        vs[m * APITCH + d] = v[src];
        hs[m * APITCH + d] = hv[src];
    }
    __syncthreads();
    {
        int l = tid >> 4, mm = tid & 15;
        float acc = 0.f;
#pragma unroll 8
        for (int k = 0; k < 256; k++) acc += qs[l * APITCH + k] * vs[mm * APITCH + k];
        ss[l * 17 + mm] = acc;
    }
    __syncthreads();
    if (tid < 16) {
        int l = tid;
        float mx = -1e30f;
#pragma unroll
        for (int mm = 0; mm < 16; mm++) mx = fmaxf(mx, ss[l * 17 + mm]);
        float s = 0.f, e[16];
#pragma unroll
        for (int mm = 0; mm < 16; mm++) { e[mm] = __expf(ss[l * 17 + mm] - mx); s += e[mm]; }
        float inv = __fdividef(1.f, s);
#pragma unroll
        for (int mm = 0; mm < 16; mm++) ss[l * 17 + mm] = e[mm] * inv;
    }
    __syncthreads();
    if (tid < 16) {
        float s = 0.f;
#pragma unroll
        for (int l = 0; l < 16; l++) s += ss[l * 17 + tid];
        ws[tid] = s;
    }
    __syncthreads();
    {
        float acc = 0.f;
#pragma unroll
        for (int mm = 0; mm < 16; mm++) acc += ws[mm] * hs[mm * APITCH + tid];
        ctx[(long)n2 * HH2 + tid] = acc;
    }
}

// =====================================================================
// Fused logits + masked CE (fast exp/log).
// =====================================================================
__global__ __launch_bounds__(256, 1)
void ce_kernel(const float* __restrict__ rnn, const float* __restrict__ ctx,
               const float* __restrict__ Wp, const float* __restrict__ bp,
               const float* __restrict__ Wk, const float* __restrict__ bk,
               const int* __restrict__ pitches, const int* __restrict__ kss,
               float* __restrict__ part) {
    extern __shared__ __align__(16) float smC[];
    float* Wps = smC;
    float* Wks = Wps + NP * 556;
    float* bps = Wks + NK * 256;
    float* bks = bps + NP;
    float* red = bks + NK;

    const int tid = threadIdx.x;
    for (int i = tid; i < NP * 556; i += 256) Wps[i] = Wp[i];
    for (int i = tid; i < NK * 256; i += 256) Wks[i] = Wk[i];
    if (tid < NP) bps[tid] = bp[tid];
    if (tid < NK) bks[tid] = bk[tid];
    __syncthreads();

    const int row = blockIdx.x * 256 + tid;
    const int t = row >> 6, b = row & 63;
    const float* xr = rnn + (long)row * 300;
    const float* xc = ctx + ((long)(b * 64 + (t >> 4))) * HH2;

    float lg[NP], lgk[NK];
#pragma unroll
    for (int c = 0; c < NP; c++) lg[c] = bps[c];
#pragma unroll
    for (int c = 0; c < NK; c++) lgk[c] = bks[c];

    for (int k4 = 0; k4 < 75; k4++) {
        float4 x = *(const float4*)&xr[k4 * 4];
#pragma unroll
        for (int c = 0; c < NP; c++) {
            const float* wr = &Wps[c * 556 + k4 * 4];
            lg[c] += wr[0] * x.x + wr[1] * x.y + wr[2] * x.z + wr[3] * x.w;
        }
    }
    for (int k4 = 0; k4 < 64; k4++) {
        float4 x = *(const float4*)&xc[k4 * 4];
#pragma unroll
        for (int c = 0; c < NP; c++) {
            const float* wr = &Wps[c * 556 + 300 + k4 * 4];
            lg[c] += wr[0] * x.x + wr[1] * x.y + wr[2] * x.z + wr[3] * x.w;
        }
#pragma unroll
        for (int c = 0; c < NK; c++) {
            const float* wr = &Wks[c * 256 + k4 * 4];
            lgk[c] += wr[0] * x.x + wr[1] * x.y + wr[2] * x.z + wr[3] * x.w;
        }
    }

    int tp = pitches[row];
    float mx = -1e30f;
#pragma unroll
    for (int c = 0; c < NP; c++) mx = fmaxf(mx, lg[c]);
    float s = 0.f;
#pragma unroll
    for (int c = 0; c < NP; c++) s += __expf(lg[c] - mx);
    float lsel = 0.f;
#pragma unroll
    for (int c = 0; c < NP; c++) lsel += (c == tp) ? lg[c] : 0.f;
    float nllp = 0.f, cp = 0.f;
    if (tp != 34) { nllp = (__logf(s) + mx) - lsel; cp = 1.f; }

    int tk = kss[row];
    float mxk = -1e30f;
#pragma unroll
    for (int c = 0; c < NK; c++) mxk = fmaxf(mxk, lgk[c]);
    float sk = 0.f;
#pragma unroll
    for (int c = 0; c < NK; c++) sk += __expf(lgk[c] - mxk);
    float ksel = 0.f;
#pragma unroll
    for (int c = 0; c < NK; c++) ksel += (c == tk) ? lgk[c] : 0.f;
    float nllk = 0.f, ck = 0.f;
    if (tk != 14) { nllk = (__logf(sk) + mxk) - ksel; ck = 1.f; }

    red[tid] = nllp; red[256 + tid] = cp; red[512 + tid] = nllk; red[768 + tid] = ck;
    __syncthreads();
    for (int off = 128; off > 0; off >>= 1) {
        if (tid < off) {
            red[tid] += red[tid + off];
            red[256 + tid] += red[256 + tid + off];
            red[512 + tid] += red[512 + tid + off];
            red[768 + tid] += red[768 + tid + off];
        }
        __syncthreads();
    }
    if (tid == 0) {
        part[blockIdx.x * 4 + 0] = red[0];
        part[blockIdx.x * 4 + 1] = red[256];
        part[blockIdx.x * 4 + 2] = red[512];
        part[blockIdx.x * 4 + 3] = red[768];
    }
}

__global__ __launch_bounds__(256)
void final_kernel(const float* __restrict__ part, float* __restrict__ out) {
    __shared__ float s0[256], s1[256], s2[256], s3[256];
    const int tid = threadIdx.x;
    s0[tid] = part[tid * 4 + 0]; s1[tid] = part[tid * 4 + 1];
    s2[tid] = part[tid * 4 + 2]; s3[tid] = part[tid * 4 + 3];
    __syncthreads();
    for (int off = 128; off > 0; off >>= 1) {
        if (tid < off) {
            s0[tid] += s0[tid + off]; s1[tid] += s1[tid + off];
            s2[tid] += s2[tid + off]; s3[tid] += s3[tid + off];
        }
        __syncthreads();
    }
    if (tid == 0) out[0] = s0[0] / fmaxf(s1[0], 1.f) + s2[0] / fmaxf(s3[0], 1.f);
}

// =====================================================================
// host
// =====================================================================
extern "C" void kernel_launch(void* const* d_in, const int* in_sizes, int n_in,
                              void* d_out, int out_size) {
    const float* sentences = (const float*)d_in[0];
    const int* pitches = (const int*)d_in[1];
    const int* kss = (const int*)d_in[2];
    const float* mWih_f = (const float*)d_in[5];
    const float* mWhh_f = (const float*)d_in[6];
    const float* mbih_f = (const float*)d_in[7];
    const float* mbhh_f = (const float*)d_in[8];
    const float* mWih_b = (const float*)d_in[9];
    const float* mWhh_b = (const float*)d_in[10];
    const float* mbih_b = (const float*)d_in[11];
    const float* mbhh_b = (const float*)d_in[12];
    const float* hWih_f = (const float*)d_in[13];
    const float* hWhh_f = (const float*)d_in[14];
    const float* hbih_f = (const float*)d_in[15];
    const float* hbhh_f = (const float*)d_in[16];
    const float* hWih_b = (const float*)d_in[17];
    const float* hWhh_b = (const float*)d_in[18];
    const float* hbih_b = (const float*)d_in[19];
    const float* hbhh_b = (const float*)d_in[20];
    const float* Wq = (const float*)d_in[21];
    const float* bq = (const float*)d_in[22];
    const float* Wv = (const float*)d_in[23];
    const float* bv = (const float*)d_in[24];
    const float* Wp = (const float*)d_in[25];
    const float* bp = (const float*)d_in[26];
    const float* Wk = (const float*)d_in[27];
    const float* bk = (const float*)d_in[28];
    float* out = (float*)d_out;

    float *p_rnn, *p_gi_hf, *p_gi_hb, *p_hier, *p_q, *p_v, *p_ctx, *p_part;
    __nv_bfloat16 *p_rhi, *p_rlo, *p_hhi, *p_hlo, *p_whh, *p_whl, *p_qvh, *p_qvl;
    cudaGetSymbolAddress((void**)&p_rnn, g_rnn);
    cudaGetSymbolAddress((void**)&p_gi_hf, g_gi_hf);
    cudaGetSymbolAddress((void**)&p_gi_hb, g_gi_hb);
    cudaGetSymbolAddress((void**)&p_hier, g_hier);
    cudaGetSymbolAddress((void**)&p_q, g_q);
    cudaGetSymbolAddress((void**)&p_v, g_v);
    cudaGetSymbolAddress((void**)&p_ctx, g_ctx);
    cudaGetSymbolAddress((void**)&p_part, g_part);
    cudaGetSymbolAddress((void**)&p_rhi, g_rnn_hi);
    cudaGetSymbolAddress((void**)&p_rlo, g_rnn_lo);
    cudaGetSymbolAddress((void**)&p_hhi, g_hier_hi);
    cudaGetSymbolAddress((void**)&p_hlo, g_hier_lo);
    cudaGetSymbolAddress((void**)&p_whh, g_wh_hi);
    cudaGetSymbolAddress((void**)&p_whl, g_wh_lo);
    cudaGetSymbolAddress((void**)&p_qvh, g_wqv_hi);
    cudaGetSymbolAddress((void**)&p_qvl, g_wqv_lo);

    const int SM_MAIN = (450 * 68 + 450 * 18 + 160 + 456 + 152 + 20) * 4;
    const int SM_HIER = (32 * 384 * 4 + 16 * 128 + 16 * 384) * 4;   // 229376
    const int SM_ATTN = (3 * 16 * APITCH + 16 * 17 + 16) * 4;
    const int SM_CE   = (NP * 556 + NK * 256 + NP + NK + 1024) * 4;
    const int SM_TG   = 2 * 65536 + 512;
    cudaFuncSetAttribute(main_gru_kernel, cudaFuncAttributeMaxDynamicSharedMemorySize, SM_MAIN);
    cudaFuncSetAttribute(hier_gru_kernel, cudaFuncAttributeMaxDynamicSharedMemorySize, SM_HIER);
    cudaFuncSetAttribute(attn_kernel, cudaFuncAttributeMaxDynamicSharedMemorySize, SM_ATTN);
    cudaFuncSetAttribute(ce_kernel, cudaFuncAttributeMaxDynamicSharedMemorySize, SM_CE);
    cudaFuncSetAttribute(tgemm_kernel, cudaFuncAttributeMaxDynamicSharedMemorySize, SM_TG);

    conv_w_kernel<<<960, 256>>>(hWih_f, hWih_b, Wq, Wv, p_whh, p_whl, p_qvh, p_qvl);
    main_gru_kernel<<<128, 480, SM_MAIN>>>(sentences, mWih_f, mWih_b, mbih_f, mbih_b,
                                           mWhh_f, mWhh_b, mbhh_f, mbhh_b,
                                           p_rnn, p_rhi, p_rlo);
    tgemm_kernel<<<dim3(3, 512, 2), 256, SM_TG>>>(p_rhi, p_rlo, p_whh, p_whl,
                                                  hbih_f, hbih_b, p_gi_hf, p_gi_hb, KP1, GH, 1);
    hier_gru_kernel<<<512, 768, SM_HIER>>>(p_gi_hf, p_gi_hb, hWhh_f, hWhh_b, hbhh_f, hbhh_b,
                                           p_hier, p_hhi, p_hlo);
    tgemm_kernel<<<dim3(2, 512, 2), 256, SM_TG>>>(p_hhi, p_hlo, p_qvh, p_qvl,
                                                  bq, bv, p_q, p_v, HH2, HH2, 0);
    attn_kernel<<<NSEG, 256, SM_ATTN>>>(p_q, p_v, p_hier, p_ctx);
    ce_kernel<<<NROW / 256, 256, SM_CE>>>(p_rnn, p_ctx, Wp, bp, Wk, bk, pitches, kss, p_part);
    final_kernel<<<1, 256>>>(p_part, out);
}